// round 9
// baseline (speedup 1.0000x reference)
#include <cuda_runtime.h>
#include <cuda_bf16.h>
#include <math.h>
#include <stdint.h>

#define BB_   2
#define SS_   2048
#define HID_  1024
#define NH_   16
#define HD_   64
#define FF_   4096
#define TOK_  (BB_*SS_)   // 4096
#define QKVLD 3072

// ---------------- scratch ----------------
__device__ __nv_bfloat16 g_h  [TOK_*HID_];
__device__ __nv_bfloat16 g_qkv[TOK_*3*HID_];       // [TOK, 3072] = q|k|v
__device__ __nv_bfloat16 g_vt [TOK_*HID_];         // [B*H, 64, S]
__device__ __nv_bfloat16 g_ctx[TOK_*HID_];
__device__ float         g_x2 [TOK_*HID_];
__device__ __nv_bfloat16 g_h2 [TOK_*HID_];
__device__ __nv_bfloat16 g_ff [TOK_*FF_];
__device__ __nv_bfloat16 g_wb [12*1024*1024];      // bf16 weights (q|k|v|o|W1|W2)
__device__ float         g_bqkv[3*HID_];

// ---------------- helpers ----------------
__device__ __forceinline__ uint32_t bf2(float x, float y) {
    __nv_bfloat162 t = __floats2bfloat162_rn(x, y);
    return *reinterpret_cast<uint32_t*>(&t);
}
__device__ __forceinline__ uint32_t smem_u32(const void* p) {
    uint32_t a;
    asm("{ .reg .u64 t; cvta.to.shared.u64 t, %1; cvt.u32.u64 %0, t; }" : "=r"(a) : "l"(p));
    return a;
}
#define CP16(dst, src) \
    asm volatile("cp.async.cg.shared.global [%0], [%1], 16;" :: "r"(dst), "l"(src) : "memory")
#define CP_COMMIT() asm volatile("cp.async.commit_group;" ::: "memory")
#define CP_WAIT1()  asm volatile("cp.async.wait_group 1;" ::: "memory")
#define CP_WAIT0()  asm volatile("cp.async.wait_group 0;" ::: "memory")

#define LDSM4(R0, R1, R2, R3, ADDR) \
    asm volatile("ldmatrix.sync.aligned.m8n8.x4.shared.b16 {%0,%1,%2,%3}, [%4];" \
        : "=r"(R0), "=r"(R1), "=r"(R2), "=r"(R3) : "r"(ADDR))

__device__ __forceinline__ void mma16816(float* c, const uint32_t* a, uint32_t b0, uint32_t b1) {
    asm volatile(
        "mma.sync.aligned.m16n8k16.row.col.f32.bf16.bf16.f32 "
        "{%0,%1,%2,%3}, {%4,%5,%6,%7}, {%8,%9}, {%0,%1,%2,%3};"
        : "+f"(c[0]), "+f"(c[1]), "+f"(c[2]), "+f"(c[3])
        : "r"(a[0]), "r"(a[1]), "r"(a[2]), "r"(a[3]), "r"(b0), "r"(b1));
}

// ---------------- bias pack ----------------
__global__ void pack_bias_kernel(const float* __restrict__ a, const float* __restrict__ b,
                                 const float* __restrict__ c, float* __restrict__ o) {
    int i = blockIdx.x * blockDim.x + threadIdx.x;
    if (i < HID_)            o[i] = a[i];
    else if (i < 2 * HID_)   o[i] = b[i - HID_];
    else if (i < 3 * HID_)   o[i] = c[i - 2 * HID_];
}

// ---------------- weight conversion fp32 -> bf16 ----------------
__global__ void round4_kernel(const float* __restrict__ a, const float* __restrict__ b,
                              const float* __restrict__ c, const float* __restrict__ d,
                              __nv_bfloat16* __restrict__ oa, __nv_bfloat16* __restrict__ ob,
                              __nv_bfloat16* __restrict__ oc, __nv_bfloat16* __restrict__ od) {
    int i = blockIdx.x * blockDim.x + threadIdx.x;
    int seg = i >> 18, off = i & 262143;
    const float4* sp; __nv_bfloat16* dp;
    if      (seg == 0) { sp = (const float4*)a; dp = oa; }
    else if (seg == 1) { sp = (const float4*)b; dp = ob; }
    else if (seg == 2) { sp = (const float4*)c; dp = oc; }
    else               { sp = (const float4*)d; dp = od; }
    float4 v = sp[off];
    reinterpret_cast<uint2*>(dp)[off] = make_uint2(bf2(v.x, v.y), bf2(v.z, v.w));
}
__global__ void round2_kernel(const float* __restrict__ a, const float* __restrict__ b,
                              __nv_bfloat16* __restrict__ oa, __nv_bfloat16* __restrict__ ob) {
    int i = blockIdx.x * blockDim.x + threadIdx.x;
    int seg = i >> 20, off = i & 1048575;
    const float4* sp = seg ? (const float4*)b : (const float4*)a;
    __nv_bfloat16* dp = seg ? ob : oa;
    float4 v = sp[off];
    reinterpret_cast<uint2*>(dp)[off] = make_uint2(bf2(v.x, v.y), bf2(v.z, v.w));
}

// ---------------- block reduction ----------------
template<bool MAX>
__device__ __forceinline__ float block_reduce_256(float v) {
    __shared__ float sh[8];
    int lane = threadIdx.x & 31, w = threadIdx.x >> 5;
    #pragma unroll
    for (int o = 16; o; o >>= 1) {
        float u = __shfl_xor_sync(0xffffffffu, v, o);
        v = MAX ? fmaxf(v, u) : v + u;
    }
    if (lane == 0) sh[w] = v;
    __syncthreads();
    if (w == 0) {
        v = sh[lane & 7];
        #pragma unroll
        for (int o = 4; o; o >>= 1) {
            float u = __shfl_xor_sync(0xffffffffu, v, o);
            v = MAX ? fmaxf(v, u) : v + u;
        }
        if (lane == 0) sh[0] = v;
    }
    __syncthreads();
    float r = sh[0];
    __syncthreads();
    return r;
}

// ---------------- LayerNorm (fp32 in -> bf16 out) ----------------
__global__ void ln_kernel(const float* __restrict__ x, const float* __restrict__ g,
                          const float* __restrict__ beta, __nv_bfloat16* __restrict__ out) {
    size_t base = (size_t)blockIdx.x * HID_;
    const float4* xp = reinterpret_cast<const float4*>(x + base);
    int t = threadIdx.x;
    float4 v = xp[t];
    float s = v.x + v.y + v.z + v.w;
    s = block_reduce_256<false>(s);
    float mean = s * (1.0f / HID_);
    float dx = v.x - mean, dy = v.y - mean, dz = v.z - mean, dw = v.w - mean;
    float q = dx*dx + dy*dy + dz*dz + dw*dw;
    q = block_reduce_256<false>(q);
    float r = rsqrtf(q * (1.0f / HID_) + 1e-5f);
    float4 gv = reinterpret_cast<const float4*>(g)[t];
    float4 bv = reinterpret_cast<const float4*>(beta)[t];
    uint2 o;
    o.x = bf2(dx * r * gv.x + bv.x, dy * r * gv.y + bv.y);
    o.y = bf2(dz * r * gv.z + bv.z, dw * r * gv.w + bv.w);
    reinterpret_cast<uint2*>(out + base)[t] = o;
}

// ---------------- transpose V ----------------
__global__ void transpose_v_kernel(const __nv_bfloat16* __restrict__ qkv,
                                   __nv_bfloat16* __restrict__ vt) {
    __shared__ __nv_bfloat16 t[32][34];
    int bz = blockIdx.y;
    int b = bz / (NH_ * 2);
    int rem = bz % (NH_ * 2);
    int h = rem >> 1;
    int d0 = (rem & 1) * 32;
    int s0 = blockIdx.x * 32;
    int tx = threadIdx.x & 31, ty = threadIdx.x >> 5;
    #pragma unroll
    for (int i = 0; i < 32; i += 8)
        t[ty + i][tx] = qkv[((size_t)b * SS_ + s0 + ty + i) * QKVLD + 2 * HID_ + h * 64 + d0 + tx];
    __syncthreads();
    #pragma unroll
    for (int i = 0; i < 32; i += 8)
        vt[(((size_t)b * NH_ + h) * 64 + d0 + ty + i) * SS_ + s0 + tx] = t[tx][ty + i];
}

// ---------------- fused flash attention (unchanged from R8) ----------------
#define FFS 72
#define FQ  0
#define FK  (128*FFS)
#define FV  (FK + 2*64*FFS)
#define FP  (FV + 2*64*FFS)
#define FL_FLT ((FP + 128*FFS) * 2)
#define FL_SMEM (FL_FLT + (2048 + 512 + 512) * 4)

__global__ __launch_bounds__(256, 1) void flash_kernel(
    const __nv_bfloat16* __restrict__ qkv, const __nv_bfloat16* __restrict__ vt,
    const float* __restrict__ am, __nv_bfloat16* __restrict__ ctx)
{
    extern __shared__ __align__(16) char smc[];
    float* Madd = reinterpret_cast<float*>(smc + FL_FLT);
    float* Pmax = Madd + 2048;
    float* Psum = Pmax + 512;

    const int tid = threadIdx.x, lane = tid & 31, wid = tid >> 5;
    const int wm = wid >> 2, wn = wid & 3;
    const int qq = lane >> 3, l8 = lane & 7;
    const int arow = ((qq & 1) << 3) + l8, acol = (qq >> 1) << 3;
    const int brow = ((qq >> 1) << 3) + l8, bcol = (qq & 1) << 3;
    const int qt = blockIdx.x, bh = blockIdx.y;
    const int bb = bh >> 4, hh = bh & 15;
    const int q0 = qt * 128;

    const __nv_bfloat16* Qg = qkv + ((size_t)bb * SS_ + q0) * QKVLD + hh * 64;
    const __nv_bfloat16* Kg = qkv + (size_t)bb * SS_ * QKVLD + HID_ + hh * 64;
    const __nv_bfloat16* Vg = vt + (size_t)bh * 64 * SS_;

    const uint32_t sb = smem_u32(smc);
    const uint32_t sQ = sb + FQ * 2, sP = sb + FP * 2;
    __nv_bfloat16* Ps = reinterpret_cast<__nv_bfloat16*>(smc) + FP;

    #pragma unroll
    for (int u = 0; u < 4; u++) {
        int idx = tid + u * 256;
        int r = idx >> 3, c8 = (idx & 7) << 3;
        CP16(sQ + (uint32_t)((r * FFS + c8) * 2), Qg + (size_t)r * QKVLD + c8);
    }
    CP_COMMIT();
    #pragma unroll
    for (int u = 0; u < 8; u++) {
        int i = tid + u * 256;
        Madd[i] = (__ldg(&am[(size_t)bb * SS_ + i]) - 1.0f) * 10000.0f;
    }

    auto load_kv = [&](int j, int s) {
        const int j0 = j * 64;
        uint32_t kb = sb + (uint32_t)((FK + s * 64 * FFS) * 2);
        uint32_t vb = sb + (uint32_t)((FV + s * 64 * FFS) * 2);
        #pragma unroll
        for (int u = 0; u < 2; u++) {
            int idx = tid + u * 256;
            int r = idx >> 3, c8 = (idx & 7) << 3;
            CP16(kb + (uint32_t)((r * FFS + c8) * 2), Kg + (size_t)(j0 + r) * QKVLD + c8);
        }
        #pragma unroll
        for (int u = 0; u < 2; u++) {
            int idx = tid + u * 256;
            int r = idx >> 3, c8 = (idx & 7) << 3;
            CP16(vb + (uint32_t)((r * FFS + c8) * 2), Vg + (size_t)r * SS_ + j0 + c8);
        }
        CP_COMMIT();
    };
    load_kv(0, 0);

    float ctxa[4][2][4] = {};
    float mrow[4][2], lrow[4][2];
    #pragma unroll
    for (int mt = 0; mt < 4; mt++) {
        mrow[mt][0] = -1e30f; mrow[mt][1] = -1e30f;
        lrow[mt][0] = 0.f;    lrow[mt][1] = 0.f;
    }

    const int IT = SS_ / 64;
    for (int j = 0; j < IT; j++) {
        const int s = j & 1;
        __syncthreads();
        if (j + 1 < IT) { load_kv(j + 1, s ^ 1); CP_WAIT1(); }
        else            { CP_WAIT0(); }
        __syncthreads();

        float sacc[4][2][4] = {};
        const uint32_t sKs = sb + (uint32_t)((FK + s * 64 * FFS) * 2);
        #pragma unroll
        for (int kk = 0; kk < 4; kk++) {
            uint32_t af[4][4];
            #pragma unroll
            for (int mt = 0; mt < 4; mt++) {
                int rr = wm * 64 + mt * 16 + arow;
                LDSM4(af[mt][0], af[mt][1], af[mt][2], af[mt][3],
                      sQ + (uint32_t)((rr * FFS + kk * 16 + acol) * 2));
            }
            uint32_t b4[4];
            {
                int nn = wn * 16 + brow;
                LDSM4(b4[0], b4[1], b4[2], b4[3],
                      sKs + (uint32_t)((nn * FFS + kk * 16 + bcol) * 2));
            }
            #pragma unroll
            for (int mt = 0; mt < 4; mt++) {
                mma16816(sacc[mt][0], af[mt], b4[0], b4[1]);
                mma16816(sacc[mt][1], af[mt], b4[2], b4[3]);
            }
        }

        const int j0 = j * 64;
        float lmax[4][2];
        #pragma unroll
        for (int mt = 0; mt < 4; mt++) { lmax[mt][0] = -1e30f; lmax[mt][1] = -1e30f; }
        #pragma unroll
        for (int nt = 0; nt < 2; nt++) {
            int cl = wn * 16 + nt * 8 + 2 * (lane & 3);
            float2 md = *reinterpret_cast<const float2*>(&Madd[j0 + cl]);
            #pragma unroll
            for (int mt = 0; mt < 4; mt++) {
                sacc[mt][nt][0] = sacc[mt][nt][0] * 0.125f + md.x;
                sacc[mt][nt][1] = sacc[mt][nt][1] * 0.125f + md.y;
                sacc[mt][nt][2] = sacc[mt][nt][2] * 0.125f + md.x;
                sacc[mt][nt][3] = sacc[mt][nt][3] * 0.125f + md.y;
                lmax[mt][0] = fmaxf(lmax[mt][0], fmaxf(sacc[mt][nt][0], sacc[mt][nt][1]));
                lmax[mt][1] = fmaxf(lmax[mt][1], fmaxf(sacc[mt][nt][2], sacc[mt][nt][3]));
            }
        }
        #pragma unroll
        for (int mt = 0; mt < 4; mt++)
            #pragma unroll
            for (int h2 = 0; h2 < 2; h2++) {
                float v = lmax[mt][h2];
                v = fmaxf(v, __shfl_xor_sync(0xffffffffu, v, 1));
                v = fmaxf(v, __shfl_xor_sync(0xffffffffu, v, 2));
                lmax[mt][h2] = v;
            }
        if ((lane & 3) == 0) {
            #pragma unroll
            for (int mt = 0; mt < 4; mt++)
                #pragma unroll
                for (int h2 = 0; h2 < 2; h2++) {
                    int row = wm * 64 + mt * 16 + h2 * 8 + (lane >> 2);
                    Pmax[wn * 128 + row] = lmax[mt][h2];
                }
        }
        __syncthreads();

        float alpha[4][2], lsum[4][2];
        #pragma unroll
        for (int mt = 0; mt < 4; mt++)
            #pragma unroll
            for (int h2 = 0; h2 < 2; h2++) {
                int row = wm * 64 + mt * 16 + h2 * 8 + (lane >> 2);
                float tm = fmaxf(fmaxf(Pmax[row], Pmax[128 + row]),
                                 fmaxf(Pmax[256 + row], Pmax[384 + row]));
                float mo = mrow[mt][h2];
                float mn = fmaxf(mo, tm);
                mrow[mt][h2]  = mn;
                alpha[mt][h2] = __expf(mo - mn);
                lsum[mt][h2]  = 0.f;
            }
        #pragma unroll
        for (int nt = 0; nt < 2; nt++) {
            int cl = wn * 16 + nt * 8 + 2 * (lane & 3);
            #pragma unroll
            for (int mt = 0; mt < 4; mt++)
                #pragma unroll
                for (int h2 = 0; h2 < 2; h2++) {
                    float p0 = __expf(sacc[mt][nt][2 * h2 + 0] - mrow[mt][h2]);
                    float p1 = __expf(sacc[mt][nt][2 * h2 + 1] - mrow[mt][h2]);
                    lsum[mt][h2] += p0 + p1;
                    int row = wm * 64 + mt * 16 + h2 * 8 + (lane >> 2);
                    *reinterpret_cast<uint32_t*>(&Ps[row * FFS + cl]) = bf2(p0, p1);
                }
        }
        #pragma unroll
        for (int mt = 0; mt < 4; mt++)
            #pragma unroll
            for (int h2 = 0; h2 < 2; h2++) {
                float v = lsum[mt][h2];
                v += __shfl_xor_sync(0xffffffffu, v, 1);
                v += __shfl_xor_sync(0xffffffffu, v, 2);
                lsum[mt][h2] = v;
            }
        if ((lane & 3) == 0) {
            #pragma unroll
            for (int mt = 0; mt < 4; mt++)
                #pragma unroll
                for (int h2 = 0; h2 < 2; h2++) {
                    int row = wm * 64 + mt * 16 + h2 * 8 + (lane >> 2);
                    Psum[wn * 128 + row] = lsum[mt][h2];
                }
        }
        __syncthreads();
        #pragma unroll
        for (int mt = 0; mt < 4; mt++)
            #pragma unroll
            for (int h2 = 0; h2 < 2; h2++) {
                int row = wm * 64 + mt * 16 + h2 * 8 + (lane >> 2);
                float ts = Psum[row] + Psum[128 + row] + Psum[256 + row] + Psum[384 + row];
                lrow[mt][h2] = lrow[mt][h2] * alpha[mt][h2] + ts;
                #pragma unroll
                for (int nt = 0; nt < 2; nt++) {
                    ctxa[mt][nt][2 * h2 + 0] *= alpha[mt][h2];
                    ctxa[mt][nt][2 * h2 + 1] *= alpha[mt][h2];
                }
            }

        const uint32_t sVs = sb + (uint32_t)((FV + s * 64 * FFS) * 2);
        #pragma unroll
        for (int kk = 0; kk < 4; kk++) {
            uint32_t af[4][4];
            #pragma unroll
            for (int mt = 0; mt < 4; mt++) {
                int rr = wm * 64 + mt * 16 + arow;
                LDSM4(af[mt][0], af[mt][1], af[mt][2], af[mt][3],
                      sP + (uint32_t)((rr * FFS + kk * 16 + acol) * 2));
            }
            uint32_t b4[4];
            {
                int nn = wn * 16 + brow;
                LDSM4(b4[0], b4[1], b4[2], b4[3],
                      sVs + (uint32_t)((nn * FFS + kk * 16 + bcol) * 2));
            }
            #pragma unroll
            for (int mt = 0; mt < 4; mt++) {
                mma16816(ctxa[mt][0], af[mt], b4[0], b4[1]);
                mma16816(ctxa[mt][1], af[mt], b4[2], b4[3]);
            }
        }
    }

    #pragma unroll
    for (int mt = 0; mt < 4; mt++)
        #pragma unroll
        for (int h2 = 0; h2 < 2; h2++) {
            int row = wm * 64 + mt * 16 + h2 * 8 + (lane >> 2);
            float inv = 1.0f / lrow[mt][h2];
            #pragma unroll
            for (int nt = 0; nt < 2; nt++) {
                int cl = wn * 16 + nt * 8 + 2 * (lane & 3);
                *reinterpret_cast<uint32_t*>(
                    ctx + ((size_t)bb * SS_ + q0 + row) * HID_ + hh * 64 + cl) =
                    bf2(ctxa[mt][nt][2 * h2 + 0] * inv, ctxa[mt][nt][2 * h2 + 1] * inv);
            }
        }
}

// ---------------- bf16 mma GEMM: 128 threads, warp tile 64x64, 3-stage ----------------
// EPI: 0 = +bias -> bf16; 2 = gelu(+bias) -> bf16; 3 = +bias+residual -> fp32
template<int EPI>
__global__ __launch_bounds__(128, 2) void tc_gemm(
    int M, int N, int K,
    const __nv_bfloat16* __restrict__ A,  int lda,
    const __nv_bfloat16* __restrict__ Bm, int ldb,
    float* __restrict__ Cf, __nv_bfloat16* __restrict__ Cb, int ldc,
    const float* __restrict__ bias, const float* __restrict__ residual)
{
    constexpr int RS  = 72;
    constexpr int ASZ = 128 * RS;
    constexpr int STG = 2 * ASZ;
    constexpr int NT  = 8;               // warp tile 64x64

    extern __shared__ __align__(16) char smc[];

    const int tid  = threadIdx.x;
    const int wid  = tid >> 5, lane = tid & 31;
    const int wm   = wid >> 1, wn = wid & 1;
    const int qq   = lane >> 3, l8 = lane & 7;
    const int arow = ((qq & 1) << 3) + l8, acol = (qq >> 1) << 3;
    const int brow = ((qq >> 1) << 3) + l8, bcol = (qq & 1) << 3;
    const int row0 = blockIdx.y * 128;
    const int col0 = blockIdx.x * 128;

    const uint32_t sbase = smem_u32(smc);

    float acc[4][NT][4];
    #pragma unroll
    for (int i = 0; i < 4; i++)
        #pragma unroll
        for (int j = 0; j < NT; j++)
            #pragma unroll
            for (int e = 0; e < 4; e++) acc[i][j][e] = 0.0f;

    const int nk = K >> 6;

    auto load_stage = [&](int i, int s) {
        const int k0 = i << 6;
        uint32_t abase = sbase + (uint32_t)(s * STG) * 2u;
        uint32_t bbase = abase + (uint32_t)ASZ * 2u;
        #pragma unroll
        for (int u = 0; u < 8; u++) {
            int idx = tid + u * 128;
            int r = idx >> 3, c8 = (idx & 7) << 3;
            CP16(abase + (uint32_t)(r * RS + c8) * 2u,
                 A + (size_t)(row0 + r) * lda + k0 + c8);
        }
        #pragma unroll
        for (int u = 0; u < 8; u++) {
            int idx = tid + u * 128;
            int r = idx >> 3, c8 = (idx & 7) << 3;
            CP16(bbase + (uint32_t)(r * RS + c8) * 2u,
                 Bm + (size_t)(col0 + r) * ldb + k0 + c8);
        }
        CP_COMMIT();
    };

    load_stage(0, 0);
    load_stage(1, 1);

    int s = 0;
    for (int i = 0; i < nk; i++) {
        if (i == nk - 1) { CP_WAIT0(); } else { CP_WAIT1(); }
        __syncthreads();
        int ns = s + 2; if (ns >= 3) ns -= 3;
        if (i + 2 < nk) load_stage(i + 2, ns);

        const uint32_t sAs = sbase + (uint32_t)(s * STG) * 2u;
        const uint32_t sBs = sAs + (uint32_t)ASZ * 2u;

        #pragma unroll
        for (int kk = 0; kk < 4; kk++) {
            uint32_t af[4][4];
            #pragma unroll
            for (int mt = 0; mt < 4; mt++) {
                int rr = wm * 64 + mt * 16 + arow;
                LDSM4(af[mt][0], af[mt][1], af[mt][2], af[mt][3],
                      sAs + (uint32_t)((rr * RS + kk * 16 + acol) * 2));
            }
            uint32_t bf[NT][2];
            #pragma unroll
            for (int ntp = 0; ntp < NT / 2; ntp++) {
                int nn = wn * 64 + ntp * 16 + brow;
                LDSM4(bf[2*ntp][0], bf[2*ntp][1], bf[2*ntp+1][0], bf[2*ntp+1][1],
                      sBs + (uint32_t)((nn * RS + kk * 16 + bcol) * 2));
            }
            #pragma unroll
            for (int nt = 0; nt < NT; nt++)
                #pragma unroll
                for (int mt = 0; mt < 4; mt++)
                    mma16816(acc[mt][nt], af[mt], bf[nt][0], bf[nt][1]);
        }
        s++; if (s == 3) s = 0;
    }

    #pragma unroll
    for (int mt = 0; mt < 4; mt++) {
        #pragma unroll
        for (int nt = 0; nt < NT; nt++) {
            int r0 = row0 + wm * 64 + mt * 16 + (lane >> 2);
            int c0 = col0 + wn * 64 + nt * 8 + 2 * (lane & 3);
            #pragma unroll
            for (int half = 0; half < 2; half++) {
                int r = r0 + half * 8;
                float v0 = acc[mt][nt][2 * half + 0];
                float v1 = acc[mt][nt][2 * half + 1];
                v0 += __ldg(&bias[c0]);
                v1 += __ldg(&bias[c0 + 1]);
                if (EPI == 2) {
                    v0 = 0.5f * v0 * (1.0f + erff(v0 * 0.70710678118654752f));
                    v1 = 0.5f * v1 * (1.0f + erff(v1 * 0.70710678118654752f));
                }
                if (EPI == 3) {
                    float2 rr = *reinterpret_cast<const float2*>(
                        residual + (size_t)r * ldc + c0);
                    v0 += rr.x; v1 += rr.y;
                    float2 o; o.x = v0; o.y = v1;
                    *reinterpret_cast<float2*>(Cf + (size_t)r * ldc + c0) = o;
                } else {
                    *reinterpret_cast<uint32_t*>(Cb + (size_t)r * ldc + c0) = bf2(v0, v1);
                }
            }
        }
    }
}

// ---------------- launch ----------------
extern "C" void kernel_launch(void* const* d_in, const int* in_sizes, int n_in,
                              void* d_out, int out_size) {
    const float* x   = (const float*)d_in[0];
    const float* am  = (const float*)d_in[1];
    const float* Wq  = (const float*)d_in[2];
    const float* bq  = (const float*)d_in[3];
    const float* Wk  = (const float*)d_in[4];
    const float* bk  = (const float*)d_in[5];
    const float* Wv  = (const float*)d_in[6];
    const float* bv  = (const float*)d_in[7];
    const float* Wo  = (const float*)d_in[8];
    const float* bo  = (const float*)d_in[9];
    const float* W1  = (const float*)d_in[10];
    const float* b1  = (const float*)d_in[11];
    const float* W2  = (const float*)d_in[12];
    const float* b2  = (const float*)d_in[13];
    const float* g1  = (const float*)d_in[14];
    const float* be1 = (const float*)d_in[15];
    const float* g2  = (const float*)d_in[16];
    const float* be2 = (const float*)d_in[17];
    float* out = (float*)d_out;

    __nv_bfloat16 *h, *qkv, *vt, *ctx, *h2, *ff, *wb;
    float *x2, *bqkv;
    cudaGetSymbolAddress((void**)&h,    g_h);
    cudaGetSymbolAddress((void**)&qkv,  g_qkv);
    cudaGetSymbolAddress((void**)&vt,   g_vt);
    cudaGetSymbolAddress((void**)&ctx,  g_ctx);
    cudaGetSymbolAddress((void**)&x2,   g_x2);
    cudaGetSymbolAddress((void**)&h2,   g_h2);
    cudaGetSymbolAddress((void**)&ff,   g_ff);
    cudaGetSymbolAddress((void**)&wb,   g_wb);
    cudaGetSymbolAddress((void**)&bqkv, g_bqkv);

    __nv_bfloat16* rWqkv = wb;
    __nv_bfloat16* rWo = wb + 3 * 1024 * 1024;
    __nv_bfloat16* rW1 = wb + 4 * 1024 * 1024;
    __nv_bfloat16* rW2 = wb + 8 * 1024 * 1024;

    const int SM3 = 3 * 2 * 128 * 72 * 2;            // 110592 bytes
    cudaFuncSetAttribute(tc_gemm<0>, cudaFuncAttributeMaxDynamicSharedMemorySize, SM3);
    cudaFuncSetAttribute(tc_gemm<2>, cudaFuncAttributeMaxDynamicSharedMemorySize, SM3);
    cudaFuncSetAttribute(tc_gemm<3>, cudaFuncAttributeMaxDynamicSharedMemorySize, SM3);
    cudaFuncSetAttribute(flash_kernel, cudaFuncAttributeMaxDynamicSharedMemorySize, FL_SMEM);

    dim3 blk(256);
    dim3 gblk(128);

    pack_bias_kernel<<<12, blk>>>(bq, bk, bv, bqkv);
    round4_kernel<<<4096, blk>>>(Wq, Wk, Wv, Wo, rWqkv, rWqkv + 1024*1024,
                                 rWqkv + 2*1024*1024, rWo);
    ln_kernel<<<TOK_, blk>>>(x, g1, be1, h);
    tc_gemm<0><<<dim3(QKVLD/128, TOK_/128), gblk, SM3>>>(TOK_, QKVLD, HID_,
        h, HID_,  rWqkv, HID_,  nullptr, qkv, QKVLD,  bqkv, nullptr);
    transpose_v_kernel<<<dim3(SS_/32, BB_*NH_*2), blk>>>(qkv, vt);
    flash_kernel<<<dim3(SS_/128, BB_*NH_), blk, FL_SMEM>>>(qkv, vt, am, ctx);
    round2_kernel<<<8192, blk>>>(W1, W2, rW1, rW2);
    tc_gemm<3><<<dim3(HID_/128, TOK_/128), gblk, SM3>>>(TOK_, HID_, HID_,
        ctx, HID_,  rWo, HID_,  x2, nullptr, HID_,  bo, x);
    ln_kernel<<<TOK_, blk>>>(x2, g2, be2, h2);
    tc_gemm<2><<<dim3(FF_/128, TOK_/128), gblk, SM3>>>(TOK_, FF_, HID_,
        h2, HID_,  rW1, HID_,  nullptr, ff, FF_,  b1, nullptr);
    tc_gemm<3><<<dim3(HID_/128, TOK_/128), gblk, SM3>>>(TOK_, HID_, FF_,
        ff, FF_,  rW2, FF_,  out, nullptr, HID_,  b2, x2);
}

// round 10
// speedup vs baseline: 1.0786x; 1.0786x over previous
#include <cuda_runtime.h>
#include <cuda_bf16.h>
#include <math.h>
#include <stdint.h>

#define BB_   2
#define SS_   2048
#define HID_  1024
#define NH_   16
#define HD_   64
#define FF_   4096
#define TOK_  (BB_*SS_)   // 4096
#define QKVLD 3072

// ---------------- scratch ----------------
__device__ __nv_bfloat16 g_h  [TOK_*HID_];
__device__ __nv_bfloat16 g_qkv[TOK_*3*HID_];       // [TOK, 3072] = q|k|v
__device__ __nv_bfloat16 g_vt [TOK_*HID_];         // [B*H, 64, S]
__device__ __nv_bfloat16 g_ctx[TOK_*HID_];
__device__ float         g_x2 [TOK_*HID_];
__device__ __nv_bfloat16 g_h2 [TOK_*HID_];
__device__ __nv_bfloat16 g_ff [TOK_*FF_];
__device__ __nv_bfloat16 g_wb [12*1024*1024];      // bf16 weights (q|k|v|o|W1|W2)
__device__ float         g_bqkv[3*HID_];

// ---------------- helpers ----------------
__device__ __forceinline__ uint32_t bf2(float x, float y) {
    __nv_bfloat162 t = __floats2bfloat162_rn(x, y);
    return *reinterpret_cast<uint32_t*>(&t);
}
__device__ __forceinline__ uint32_t smem_u32(const void* p) {
    uint32_t a;
    asm("{ .reg .u64 t; cvta.to.shared.u64 t, %1; cvt.u32.u64 %0, t; }" : "=r"(a) : "l"(p));
    return a;
}
#define CP16(dst, src) \
    asm volatile("cp.async.cg.shared.global [%0], [%1], 16;" :: "r"(dst), "l"(src) : "memory")
#define CP_COMMIT() asm volatile("cp.async.commit_group;" ::: "memory")
#define CP_WAIT1()  asm volatile("cp.async.wait_group 1;" ::: "memory")
#define CP_WAIT0()  asm volatile("cp.async.wait_group 0;" ::: "memory")

#define LDSM4(R0, R1, R2, R3, ADDR) \
    asm volatile("ldmatrix.sync.aligned.m8n8.x4.shared.b16 {%0,%1,%2,%3}, [%4];" \
        : "=r"(R0), "=r"(R1), "=r"(R2), "=r"(R3) : "r"(ADDR))

__device__ __forceinline__ void mma16816(float* c, const uint32_t* a, uint32_t b0, uint32_t b1) {
    asm volatile(
        "mma.sync.aligned.m16n8k16.row.col.f32.bf16.bf16.f32 "
        "{%0,%1,%2,%3}, {%4,%5,%6,%7}, {%8,%9}, {%0,%1,%2,%3};"
        : "+f"(c[0]), "+f"(c[1]), "+f"(c[2]), "+f"(c[3])
        : "r"(a[0]), "r"(a[1]), "r"(a[2]), "r"(a[3]), "r"(b0), "r"(b1));
}

// ---------------- bias pack ----------------
__global__ void pack_bias_kernel(const float* __restrict__ a, const float* __restrict__ b,
                                 const float* __restrict__ c, float* __restrict__ o) {
    int i = blockIdx.x * blockDim.x + threadIdx.x;
    if (i < HID_)            o[i] = a[i];
    else if (i < 2 * HID_)   o[i] = b[i - HID_];
    else if (i < 3 * HID_)   o[i] = c[i - 2 * HID_];
}

// ---------------- weight conversion fp32 -> bf16 ----------------
__global__ void round4_kernel(const float* __restrict__ a, const float* __restrict__ b,
                              const float* __restrict__ c, const float* __restrict__ d,
                              __nv_bfloat16* __restrict__ oa, __nv_bfloat16* __restrict__ ob,
                              __nv_bfloat16* __restrict__ oc, __nv_bfloat16* __restrict__ od) {
    int i = blockIdx.x * blockDim.x + threadIdx.x;
    int seg = i >> 18, off = i & 262143;
    const float4* sp; __nv_bfloat16* dp;
    if      (seg == 0) { sp = (const float4*)a; dp = oa; }
    else if (seg == 1) { sp = (const float4*)b; dp = ob; }
    else if (seg == 2) { sp = (const float4*)c; dp = oc; }
    else               { sp = (const float4*)d; dp = od; }
    float4 v = sp[off];
    reinterpret_cast<uint2*>(dp)[off] = make_uint2(bf2(v.x, v.y), bf2(v.z, v.w));
}
__global__ void round2_kernel(const float* __restrict__ a, const float* __restrict__ b,
                              __nv_bfloat16* __restrict__ oa, __nv_bfloat16* __restrict__ ob) {
    int i = blockIdx.x * blockDim.x + threadIdx.x;
    int seg = i >> 20, off = i & 1048575;
    const float4* sp = seg ? (const float4*)b : (const float4*)a;
    __nv_bfloat16* dp = seg ? ob : oa;
    float4 v = sp[off];
    reinterpret_cast<uint2*>(dp)[off] = make_uint2(bf2(v.x, v.y), bf2(v.z, v.w));
}

// ---------------- block reduction ----------------
template<bool MAX>
__device__ __forceinline__ float block_reduce_256(float v) {
    __shared__ float sh[8];
    int lane = threadIdx.x & 31, w = threadIdx.x >> 5;
    #pragma unroll
    for (int o = 16; o; o >>= 1) {
        float u = __shfl_xor_sync(0xffffffffu, v, o);
        v = MAX ? fmaxf(v, u) : v + u;
    }
    if (lane == 0) sh[w] = v;
    __syncthreads();
    if (w == 0) {
        v = sh[lane & 7];
        #pragma unroll
        for (int o = 4; o; o >>= 1) {
            float u = __shfl_xor_sync(0xffffffffu, v, o);
            v = MAX ? fmaxf(v, u) : v + u;
        }
        if (lane == 0) sh[0] = v;
    }
    __syncthreads();
    float r = sh[0];
    __syncthreads();
    return r;
}

// ---------------- LayerNorm (fp32 in -> bf16 out) ----------------
__global__ void ln_kernel(const float* __restrict__ x, const float* __restrict__ g,
                          const float* __restrict__ beta, __nv_bfloat16* __restrict__ out) {
    size_t base = (size_t)blockIdx.x * HID_;
    const float4* xp = reinterpret_cast<const float4*>(x + base);
    int t = threadIdx.x;
    float4 v = xp[t];
    float s = v.x + v.y + v.z + v.w;
    s = block_reduce_256<false>(s);
    float mean = s * (1.0f / HID_);
    float dx = v.x - mean, dy = v.y - mean, dz = v.z - mean, dw = v.w - mean;
    float q = dx*dx + dy*dy + dz*dz + dw*dw;
    q = block_reduce_256<false>(q);
    float r = rsqrtf(q * (1.0f / HID_) + 1e-5f);
    float4 gv = reinterpret_cast<const float4*>(g)[t];
    float4 bv = reinterpret_cast<const float4*>(beta)[t];
    uint2 o;
    o.x = bf2(dx * r * gv.x + bv.x, dy * r * gv.y + bv.y);
    o.y = bf2(dz * r * gv.z + bv.z, dw * r * gv.w + bv.w);
    reinterpret_cast<uint2*>(out + base)[t] = o;
}

// ---------------- transpose V ----------------
__global__ void transpose_v_kernel(const __nv_bfloat16* __restrict__ qkv,
                                   __nv_bfloat16* __restrict__ vt) {
    __shared__ __nv_bfloat16 t[32][34];
    int bz = blockIdx.y;
    int b = bz / (NH_ * 2);
    int rem = bz % (NH_ * 2);
    int h = rem >> 1;
    int d0 = (rem & 1) * 32;
    int s0 = blockIdx.x * 32;
    int tx = threadIdx.x & 31, ty = threadIdx.x >> 5;
    #pragma unroll
    for (int i = 0; i < 32; i += 8)
        t[ty + i][tx] = qkv[((size_t)b * SS_ + s0 + ty + i) * QKVLD + 2 * HID_ + h * 64 + d0 + tx];
    __syncthreads();
    #pragma unroll
    for (int i = 0; i < 32; i += 8)
        vt[(((size_t)b * NH_ + h) * 64 + d0 + ty + i) * SS_ + s0 + tx] = t[tx][ty + i];
}

// ---------------- fused flash attention (now 2 CTAs/SM) ----------------
#define FFS 72
#define FQ  0
#define FK  (128*FFS)
#define FV  (FK + 2*64*FFS)
#define FP  (FV + 2*64*FFS)
#define FL_FLT ((FP + 128*FFS) * 2)
#define FL_SMEM (FL_FLT + (2048 + 512 + 512) * 4)

__global__ __launch_bounds__(256, 2) void flash_kernel(
    const __nv_bfloat16* __restrict__ qkv, const __nv_bfloat16* __restrict__ vt,
    const float* __restrict__ am, __nv_bfloat16* __restrict__ ctx)
{
    extern __shared__ __align__(16) char smc[];
    float* Madd = reinterpret_cast<float*>(smc + FL_FLT);
    float* Pmax = Madd + 2048;
    float* Psum = Pmax + 512;

    const int tid = threadIdx.x, lane = tid & 31, wid = tid >> 5;
    const int wm = wid >> 2, wn = wid & 3;
    const int qq = lane >> 3, l8 = lane & 7;
    const int arow = ((qq & 1) << 3) + l8, acol = (qq >> 1) << 3;
    const int brow = ((qq >> 1) << 3) + l8, bcol = (qq & 1) << 3;
    const int qt = blockIdx.x, bh = blockIdx.y;
    const int bb = bh >> 4, hh = bh & 15;
    const int q0 = qt * 128;

    const __nv_bfloat16* Qg = qkv + ((size_t)bb * SS_ + q0) * QKVLD + hh * 64;
    const __nv_bfloat16* Kg = qkv + (size_t)bb * SS_ * QKVLD + HID_ + hh * 64;
    const __nv_bfloat16* Vg = vt + (size_t)bh * 64 * SS_;

    const uint32_t sb = smem_u32(smc);
    const uint32_t sQ = sb + FQ * 2, sP = sb + FP * 2;
    __nv_bfloat16* Ps = reinterpret_cast<__nv_bfloat16*>(smc) + FP;

    #pragma unroll
    for (int u = 0; u < 4; u++) {
        int idx = tid + u * 256;
        int r = idx >> 3, c8 = (idx & 7) << 3;
        CP16(sQ + (uint32_t)((r * FFS + c8) * 2), Qg + (size_t)r * QKVLD + c8);
    }
    CP_COMMIT();
    #pragma unroll
    for (int u = 0; u < 8; u++) {
        int i = tid + u * 256;
        Madd[i] = (__ldg(&am[(size_t)bb * SS_ + i]) - 1.0f) * 10000.0f;
    }

    auto load_kv = [&](int j, int s) {
        const int j0 = j * 64;
        uint32_t kb = sb + (uint32_t)((FK + s * 64 * FFS) * 2);
        uint32_t vb = sb + (uint32_t)((FV + s * 64 * FFS) * 2);
        #pragma unroll
        for (int u = 0; u < 2; u++) {
            int idx = tid + u * 256;
            int r = idx >> 3, c8 = (idx & 7) << 3;
            CP16(kb + (uint32_t)((r * FFS + c8) * 2), Kg + (size_t)(j0 + r) * QKVLD + c8);
        }
        #pragma unroll
        for (int u = 0; u < 2; u++) {
            int idx = tid + u * 256;
            int r = idx >> 3, c8 = (idx & 7) << 3;
            CP16(vb + (uint32_t)((r * FFS + c8) * 2), Vg + (size_t)r * SS_ + j0 + c8);
        }
        CP_COMMIT();
    };
    load_kv(0, 0);

    float ctxa[4][2][4] = {};
    float mrow[4][2], lrow[4][2];
    #pragma unroll
    for (int mt = 0; mt < 4; mt++) {
        mrow[mt][0] = -1e30f; mrow[mt][1] = -1e30f;
        lrow[mt][0] = 0.f;    lrow[mt][1] = 0.f;
    }

    const int IT = SS_ / 64;
    for (int j = 0; j < IT; j++) {
        const int s = j & 1;
        __syncthreads();
        if (j + 1 < IT) { load_kv(j + 1, s ^ 1); CP_WAIT1(); }
        else            { CP_WAIT0(); }
        __syncthreads();

        float sacc[4][2][4] = {};
        const uint32_t sKs = sb + (uint32_t)((FK + s * 64 * FFS) * 2);
        #pragma unroll
        for (int kk = 0; kk < 4; kk++) {
            uint32_t af[4][4];
            #pragma unroll
            for (int mt = 0; mt < 4; mt++) {
                int rr = wm * 64 + mt * 16 + arow;
                LDSM4(af[mt][0], af[mt][1], af[mt][2], af[mt][3],
                      sQ + (uint32_t)((rr * FFS + kk * 16 + acol) * 2));
            }
            uint32_t b4[4];
            {
                int nn = wn * 16 + brow;
                LDSM4(b4[0], b4[1], b4[2], b4[3],
                      sKs + (uint32_t)((nn * FFS + kk * 16 + bcol) * 2));
            }
            #pragma unroll
            for (int mt = 0; mt < 4; mt++) {
                mma16816(sacc[mt][0], af[mt], b4[0], b4[1]);
                mma16816(sacc[mt][1], af[mt], b4[2], b4[3]);
            }
        }

        const int j0 = j * 64;
        float lmax[4][2];
        #pragma unroll
        for (int mt = 0; mt < 4; mt++) { lmax[mt][0] = -1e30f; lmax[mt][1] = -1e30f; }
        #pragma unroll
        for (int nt = 0; nt < 2; nt++) {
            int cl = wn * 16 + nt * 8 + 2 * (lane & 3);
            float2 md = *reinterpret_cast<const float2*>(&Madd[j0 + cl]);
            #pragma unroll
            for (int mt = 0; mt < 4; mt++) {
                sacc[mt][nt][0] = sacc[mt][nt][0] * 0.125f + md.x;
                sacc[mt][nt][1] = sacc[mt][nt][1] * 0.125f + md.y;
                sacc[mt][nt][2] = sacc[mt][nt][2] * 0.125f + md.x;
                sacc[mt][nt][3] = sacc[mt][nt][3] * 0.125f + md.y;
                lmax[mt][0] = fmaxf(lmax[mt][0], fmaxf(sacc[mt][nt][0], sacc[mt][nt][1]));
                lmax[mt][1] = fmaxf(lmax[mt][1], fmaxf(sacc[mt][nt][2], sacc[mt][nt][3]));
            }
        }
        #pragma unroll
        for (int mt = 0; mt < 4; mt++)
            #pragma unroll
            for (int h2 = 0; h2 < 2; h2++) {
                float v = lmax[mt][h2];
                v = fmaxf(v, __shfl_xor_sync(0xffffffffu, v, 1));
                v = fmaxf(v, __shfl_xor_sync(0xffffffffu, v, 2));
                lmax[mt][h2] = v;
            }
        if ((lane & 3) == 0) {
            #pragma unroll
            for (int mt = 0; mt < 4; mt++)
                #pragma unroll
                for (int h2 = 0; h2 < 2; h2++) {
                    int row = wm * 64 + mt * 16 + h2 * 8 + (lane >> 2);
                    Pmax[wn * 128 + row] = lmax[mt][h2];
                }
        }
        __syncthreads();

        float alpha[4][2], lsum[4][2];
        #pragma unroll
        for (int mt = 0; mt < 4; mt++)
            #pragma unroll
            for (int h2 = 0; h2 < 2; h2++) {
                int row = wm * 64 + mt * 16 + h2 * 8 + (lane >> 2);
                float tm = fmaxf(fmaxf(Pmax[row], Pmax[128 + row]),
                                 fmaxf(Pmax[256 + row], Pmax[384 + row]));
                float mo = mrow[mt][h2];
                float mn = fmaxf(mo, tm);
                mrow[mt][h2]  = mn;
                alpha[mt][h2] = __expf(mo - mn);
                lsum[mt][h2]  = 0.f;
            }
        #pragma unroll
        for (int nt = 0; nt < 2; nt++) {
            int cl = wn * 16 + nt * 8 + 2 * (lane & 3);
            #pragma unroll
            for (int mt = 0; mt < 4; mt++)
                #pragma unroll
                for (int h2 = 0; h2 < 2; h2++) {
                    float p0 = __expf(sacc[mt][nt][2 * h2 + 0] - mrow[mt][h2]);
                    float p1 = __expf(sacc[mt][nt][2 * h2 + 1] - mrow[mt][h2]);
                    lsum[mt][h2] += p0 + p1;
                    int row = wm * 64 + mt * 16 + h2 * 8 + (lane >> 2);
                    *reinterpret_cast<uint32_t*>(&Ps[row * FFS + cl]) = bf2(p0, p1);
                }
        }
        #pragma unroll
        for (int mt = 0; mt < 4; mt++)
            #pragma unroll
            for (int h2 = 0; h2 < 2; h2++) {
                float v = lsum[mt][h2];
                v += __shfl_xor_sync(0xffffffffu, v, 1);
                v += __shfl_xor_sync(0xffffffffu, v, 2);
                lsum[mt][h2] = v;
            }
        if ((lane & 3) == 0) {
            #pragma unroll
            for (int mt = 0; mt < 4; mt++)
                #pragma unroll
                for (int h2 = 0; h2 < 2; h2++) {
                    int row = wm * 64 + mt * 16 + h2 * 8 + (lane >> 2);
                    Psum[wn * 128 + row] = lsum[mt][h2];
                }
        }
        __syncthreads();
        #pragma unroll
        for (int mt = 0; mt < 4; mt++)
            #pragma unroll
            for (int h2 = 0; h2 < 2; h2++) {
                int row = wm * 64 + mt * 16 + h2 * 8 + (lane >> 2);
                float ts = Psum[row] + Psum[128 + row] + Psum[256 + row] + Psum[384 + row];
                lrow[mt][h2] = lrow[mt][h2] * alpha[mt][h2] + ts;
                #pragma unroll
                for (int nt = 0; nt < 2; nt++) {
                    ctxa[mt][nt][2 * h2 + 0] *= alpha[mt][h2];
                    ctxa[mt][nt][2 * h2 + 1] *= alpha[mt][h2];
                }
            }

        const uint32_t sVs = sb + (uint32_t)((FV + s * 64 * FFS) * 2);
        #pragma unroll
        for (int kk = 0; kk < 4; kk++) {
            uint32_t af[4][4];
            #pragma unroll
            for (int mt = 0; mt < 4; mt++) {
                int rr = wm * 64 + mt * 16 + arow;
                LDSM4(af[mt][0], af[mt][1], af[mt][2], af[mt][3],
                      sP + (uint32_t)((rr * FFS + kk * 16 + acol) * 2));
            }
            uint32_t b4[4];
            {
                int nn = wn * 16 + brow;
                LDSM4(b4[0], b4[1], b4[2], b4[3],
                      sVs + (uint32_t)((nn * FFS + kk * 16 + bcol) * 2));
            }
            #pragma unroll
            for (int mt = 0; mt < 4; mt++) {
                mma16816(ctxa[mt][0], af[mt], b4[0], b4[1]);
                mma16816(ctxa[mt][1], af[mt], b4[2], b4[3]);
            }
        }
    }

    #pragma unroll
    for (int mt = 0; mt < 4; mt++)
        #pragma unroll
        for (int h2 = 0; h2 < 2; h2++) {
            int row = wm * 64 + mt * 16 + h2 * 8 + (lane >> 2);
            float inv = 1.0f / lrow[mt][h2];
            #pragma unroll
            for (int nt = 0; nt < 2; nt++) {
                int cl = wn * 16 + nt * 8 + 2 * (lane & 3);
                *reinterpret_cast<uint32_t*>(
                    ctx + ((size_t)bb * SS_ + q0 + row) * HID_ + hh * 64 + cl) =
                    bf2(ctxa[mt][nt][2 * h2 + 0] * inv, ctxa[mt][nt][2 * h2 + 1] * inv);
            }
        }
}

// ---------------- bf16 mma GEMM: R8 config (256 thr, warp tile 64x32, 3-stage) ----------------
// EPI: 0 = +bias -> bf16; 2 = gelu(+bias) -> bf16; 3 = +bias+residual -> fp32
template<int EPI>
__global__ __launch_bounds__(256, 2) void tc_gemm(
    int M, int N, int K,
    const __nv_bfloat16* __restrict__ A,  int lda,
    const __nv_bfloat16* __restrict__ Bm, int ldb,
    float* __restrict__ Cf, __nv_bfloat16* __restrict__ Cb, int ldc,
    const float* __restrict__ bias, const float* __restrict__ residual)
{
    constexpr int RS  = 72;
    constexpr int ASZ = 128 * RS;
    constexpr int STG = 2 * ASZ;
    constexpr int NT  = 4;

    extern __shared__ __align__(16) char smc[];

    const int tid  = threadIdx.x;
    const int wid  = tid >> 5, lane = tid & 31;
    const int wm   = wid >> 2, wn = wid & 3;
    const int qq   = lane >> 3, l8 = lane & 7;
    const int arow = ((qq & 1) << 3) + l8, acol = (qq >> 1) << 3;
    const int brow = ((qq >> 1) << 3) + l8, bcol = (qq & 1) << 3;
    const int row0 = blockIdx.y * 128;
    const int col0 = blockIdx.x * 128;

    const uint32_t sbase = smem_u32(smc);

    float acc[4][NT][4];
    #pragma unroll
    for (int i = 0; i < 4; i++)
        #pragma unroll
        for (int j = 0; j < NT; j++)
            #pragma unroll
            for (int e = 0; e < 4; e++) acc[i][j][e] = 0.0f;

    const int nk = K >> 6;

    auto load_stage = [&](int i, int s) {
        const int k0 = i << 6;
        uint32_t abase = sbase + (uint32_t)(s * STG) * 2u;
        uint32_t bbase = abase + (uint32_t)ASZ * 2u;
        #pragma unroll
        for (int u = 0; u < 4; u++) {
            int idx = tid + u * 256;
            int r = idx >> 3, c8 = (idx & 7) << 3;
            CP16(abase + (uint32_t)(r * RS + c8) * 2u,
                 A + (size_t)(row0 + r) * lda + k0 + c8);
        }
        #pragma unroll
        for (int u = 0; u < 4; u++) {
            int idx = tid + u * 256;
            int r = idx >> 3, c8 = (idx & 7) << 3;
            CP16(bbase + (uint32_t)(r * RS + c8) * 2u,
                 Bm + (size_t)(col0 + r) * ldb + k0 + c8);
        }
        CP_COMMIT();
    };

    load_stage(0, 0);
    load_stage(1, 1);

    int s = 0;
    for (int i = 0; i < nk; i++) {
        if (i == nk - 1) { CP_WAIT0(); } else { CP_WAIT1(); }
        __syncthreads();
        int ns = s + 2; if (ns >= 3) ns -= 3;
        if (i + 2 < nk) load_stage(i + 2, ns);

        const uint32_t sAs = sbase + (uint32_t)(s * STG) * 2u;
        const uint32_t sBs = sAs + (uint32_t)ASZ * 2u;

        #pragma unroll
        for (int kk = 0; kk < 4; kk++) {
            uint32_t af[4][4];
            #pragma unroll
            for (int mt = 0; mt < 4; mt++) {
                int rr = wm * 64 + mt * 16 + arow;
                LDSM4(af[mt][0], af[mt][1], af[mt][2], af[mt][3],
                      sAs + (uint32_t)((rr * RS + kk * 16 + acol) * 2));
            }
            uint32_t bf[NT][2];
            #pragma unroll
            for (int ntp = 0; ntp < NT / 2; ntp++) {
                int nn = wn * 32 + ntp * 16 + brow;
                LDSM4(bf[2*ntp][0], bf[2*ntp][1], bf[2*ntp+1][0], bf[2*ntp+1][1],
                      sBs + (uint32_t)((nn * RS + kk * 16 + bcol) * 2));
            }
            #pragma unroll
            for (int nt = 0; nt < NT; nt++)
                #pragma unroll
                for (int mt = 0; mt < 4; mt++)
                    mma16816(acc[mt][nt], af[mt], bf[nt][0], bf[nt][1]);
        }
        s++; if (s == 3) s = 0;
    }

    #pragma unroll
    for (int mt = 0; mt < 4; mt++) {
        #pragma unroll
        for (int nt = 0; nt < NT; nt++) {
            int r0 = row0 + wm * 64 + mt * 16 + (lane >> 2);
            int c0 = col0 + wn * 32 + nt * 8 + 2 * (lane & 3);
            #pragma unroll
            for (int half = 0; half < 2; half++) {
                int r = r0 + half * 8;
                float v0 = acc[mt][nt][2 * half + 0];
                float v1 = acc[mt][nt][2 * half + 1];
                v0 += __ldg(&bias[c0]);
                v1 += __ldg(&bias[c0 + 1]);
                if (EPI == 2) {
                    v0 = 0.5f * v0 * (1.0f + erff(v0 * 0.70710678118654752f));
                    v1 = 0.5f * v1 * (1.0f + erff(v1 * 0.70710678118654752f));
                }
                if (EPI == 3) {
                    float2 rr = *reinterpret_cast<const float2*>(
                        residual + (size_t)r * ldc + c0);
                    v0 += rr.x; v1 += rr.y;
                    float2 o; o.x = v0; o.y = v1;
                    *reinterpret_cast<float2*>(Cf + (size_t)r * ldc + c0) = o;
                } else {
                    *reinterpret_cast<uint32_t*>(Cb + (size_t)r * ldc + c0) = bf2(v0, v1);
                }
            }
        }
    }
}

// ---------------- launch ----------------
extern "C" void kernel_launch(void* const* d_in, const int* in_sizes, int n_in,
                              void* d_out, int out_size) {
    const float* x   = (const float*)d_in[0];
    const float* am  = (const float*)d_in[1];
    const float* Wq  = (const float*)d_in[2];
    const float* bq  = (const float*)d_in[3];
    const float* Wk  = (const float*)d_in[4];
    const float* bk  = (const float*)d_in[5];
    const float* Wv  = (const float*)d_in[6];
    const float* bv  = (const float*)d_in[7];
    const float* Wo  = (const float*)d_in[8];
    const float* bo  = (const float*)d_in[9];
    const float* W1  = (const float*)d_in[10];
    const float* b1  = (const float*)d_in[11];
    const float* W2  = (const float*)d_in[12];
    const float* b2  = (const float*)d_in[13];
    const float* g1  = (const float*)d_in[14];
    const float* be1 = (const float*)d_in[15];
    const float* g2  = (const float*)d_in[16];
    const float* be2 = (const float*)d_in[17];
    float* out = (float*)d_out;

    __nv_bfloat16 *h, *qkv, *vt, *ctx, *h2, *ff, *wb;
    float *x2, *bqkv;
    cudaGetSymbolAddress((void**)&h,    g_h);
    cudaGetSymbolAddress((void**)&qkv,  g_qkv);
    cudaGetSymbolAddress((void**)&vt,   g_vt);
    cudaGetSymbolAddress((void**)&ctx,  g_ctx);
    cudaGetSymbolAddress((void**)&x2,   g_x2);
    cudaGetSymbolAddress((void**)&h2,   g_h2);
    cudaGetSymbolAddress((void**)&ff,   g_ff);
    cudaGetSymbolAddress((void**)&wb,   g_wb);
    cudaGetSymbolAddress((void**)&bqkv, g_bqkv);

    __nv_bfloat16* rWqkv = wb;
    __nv_bfloat16* rWo = wb + 3 * 1024 * 1024;
    __nv_bfloat16* rW1 = wb + 4 * 1024 * 1024;
    __nv_bfloat16* rW2 = wb + 8 * 1024 * 1024;

    const int SM3 = 3 * 2 * 128 * 72 * 2;            // 110592 bytes
    cudaFuncSetAttribute(tc_gemm<0>, cudaFuncAttributeMaxDynamicSharedMemorySize, SM3);
    cudaFuncSetAttribute(tc_gemm<2>, cudaFuncAttributeMaxDynamicSharedMemorySize, SM3);
    cudaFuncSetAttribute(tc_gemm<3>, cudaFuncAttributeMaxDynamicSharedMemorySize, SM3);
    cudaFuncSetAttribute(flash_kernel, cudaFuncAttributeMaxDynamicSharedMemorySize, FL_SMEM);

    dim3 blk(256);

    pack_bias_kernel<<<12, blk>>>(bq, bk, bv, bqkv);
    round4_kernel<<<4096, blk>>>(Wq, Wk, Wv, Wo, rWqkv, rWqkv + 1024*1024,
                                 rWqkv + 2*1024*1024, rWo);
    ln_kernel<<<TOK_, blk>>>(x, g1, be1, h);
    tc_gemm<0><<<dim3(QKVLD/128, TOK_/128), blk, SM3>>>(TOK_, QKVLD, HID_,
        h, HID_,  rWqkv, HID_,  nullptr, qkv, QKVLD,  bqkv, nullptr);
    transpose_v_kernel<<<dim3(SS_/32, BB_*NH_*2), blk>>>(qkv, vt);
    flash_kernel<<<dim3(SS_/128, BB_*NH_), blk, FL_SMEM>>>(qkv, vt, am, ctx);
    round2_kernel<<<8192, blk>>>(W1, W2, rW1, rW2);
    tc_gemm<3><<<dim3(HID_/128, TOK_/128), blk, SM3>>>(TOK_, HID_, HID_,
        ctx, HID_,  rWo, HID_,  x2, nullptr, HID_,  bo, x);
    ln_kernel<<<TOK_, blk>>>(x2, g2, be2, h2);
    tc_gemm<2><<<dim3(FF_/128, TOK_/128), blk, SM3>>>(TOK_, FF_, HID_,
        h2, HID_,  rW1, HID_,  nullptr, ff, FF_,  b1, nullptr);
    tc_gemm<3><<<dim3(HID_/128, TOK_/128), blk, SM3>>>(TOK_, HID_, FF_,
        ff, FF_,  rW2, FF_,  out, nullptr, HID_,  b2, x2);
}

// round 11
// speedup vs baseline: 1.1535x; 1.0695x over previous
#include <cuda_runtime.h>
#include <cuda_bf16.h>
#include <math.h>
#include <stdint.h>

#define BB_   2
#define SS_   2048
#define HID_  1024
#define NH_   16
#define HD_   64
#define FF_   4096
#define TOK_  (BB_*SS_)   // 4096
#define QKVLD 3072

// ---------------- scratch ----------------
__device__ __nv_bfloat16 g_h  [TOK_*HID_];
__device__ __nv_bfloat16 g_qkv[TOK_*3*HID_];       // [TOK, 3072] = q|k|v
__device__ __nv_bfloat16 g_vt [TOK_*HID_];         // [B*H, 64, S]
__device__ __nv_bfloat16 g_ctx[TOK_*HID_];
__device__ float         g_x2 [TOK_*HID_];
__device__ __nv_bfloat16 g_h2 [TOK_*HID_];
__device__ __nv_bfloat16 g_ff [TOK_*FF_];
__device__ __nv_bfloat16 g_wb [12*1024*1024];      // bf16 weights (q|k|v|o|W1|W2)
__device__ float         g_bqkv[3*HID_];

// ---------------- helpers ----------------
__device__ __forceinline__ uint32_t bf2(float x, float y) {
    __nv_bfloat162 t = __floats2bfloat162_rn(x, y);
    return *reinterpret_cast<uint32_t*>(&t);
}
__device__ __forceinline__ uint32_t smem_u32(const void* p) {
    uint32_t a;
    asm("{ .reg .u64 t; cvta.to.shared.u64 t, %1; cvt.u32.u64 %0, t; }" : "=r"(a) : "l"(p));
    return a;
}
#define CP16(dst, src) \
    asm volatile("cp.async.cg.shared.global [%0], [%1], 16;" :: "r"(dst), "l"(src) : "memory")
#define CP_COMMIT() asm volatile("cp.async.commit_group;" ::: "memory")
#define CP_WAIT1()  asm volatile("cp.async.wait_group 1;" ::: "memory")
#define CP_WAIT0()  asm volatile("cp.async.wait_group 0;" ::: "memory")

#define LDSM4(R0, R1, R2, R3, ADDR) \
    asm volatile("ldmatrix.sync.aligned.m8n8.x4.shared.b16 {%0,%1,%2,%3}, [%4];" \
        : "=r"(R0), "=r"(R1), "=r"(R2), "=r"(R3) : "r"(ADDR))

__device__ __forceinline__ void mma16816(float* c, const uint32_t* a, uint32_t b0, uint32_t b1) {
    asm volatile(
        "mma.sync.aligned.m16n8k16.row.col.f32.bf16.bf16.f32 "
        "{%0,%1,%2,%3}, {%4,%5,%6,%7}, {%8,%9}, {%0,%1,%2,%3};"
        : "+f"(c[0]), "+f"(c[1]), "+f"(c[2]), "+f"(c[3])
        : "r"(a[0]), "r"(a[1]), "r"(a[2]), "r"(a[3]), "r"(b0), "r"(b1));
}

// ---------------- bias pack ----------------
__global__ void pack_bias_kernel(const float* __restrict__ a, const float* __restrict__ b,
                                 const float* __restrict__ c, float* __restrict__ o) {
    int i = blockIdx.x * blockDim.x + threadIdx.x;
    if (i < HID_)            o[i] = a[i];
    else if (i < 2 * HID_)   o[i] = b[i - HID_];
    else if (i < 3 * HID_)   o[i] = c[i - 2 * HID_];
}

// ---------------- weight conversion fp32 -> bf16 ----------------
__global__ void round4_kernel(const float* __restrict__ a, const float* __restrict__ b,
                              const float* __restrict__ c, const float* __restrict__ d,
                              __nv_bfloat16* __restrict__ oa, __nv_bfloat16* __restrict__ ob,
                              __nv_bfloat16* __restrict__ oc, __nv_bfloat16* __restrict__ od) {
    int i = blockIdx.x * blockDim.x + threadIdx.x;
    int seg = i >> 18, off = i & 262143;
    const float4* sp; __nv_bfloat16* dp;
    if      (seg == 0) { sp = (const float4*)a; dp = oa; }
    else if (seg == 1) { sp = (const float4*)b; dp = ob; }
    else if (seg == 2) { sp = (const float4*)c; dp = oc; }
    else               { sp = (const float4*)d; dp = od; }
    float4 v = sp[off];
    reinterpret_cast<uint2*>(dp)[off] = make_uint2(bf2(v.x, v.y), bf2(v.z, v.w));
}
__global__ void round2_kernel(const float* __restrict__ a, const float* __restrict__ b,
                              __nv_bfloat16* __restrict__ oa, __nv_bfloat16* __restrict__ ob) {
    int i = blockIdx.x * blockDim.x + threadIdx.x;
    int seg = i >> 20, off = i & 1048575;
    const float4* sp = seg ? (const float4*)b : (const float4*)a;
    __nv_bfloat16* dp = seg ? ob : oa;
    float4 v = sp[off];
    reinterpret_cast<uint2*>(dp)[off] = make_uint2(bf2(v.x, v.y), bf2(v.z, v.w));
}

// ---------------- block reduction ----------------
template<bool MAX>
__device__ __forceinline__ float block_reduce_256(float v) {
    __shared__ float sh[8];
    int lane = threadIdx.x & 31, w = threadIdx.x >> 5;
    #pragma unroll
    for (int o = 16; o; o >>= 1) {
        float u = __shfl_xor_sync(0xffffffffu, v, o);
        v = MAX ? fmaxf(v, u) : v + u;
    }
    if (lane == 0) sh[w] = v;
    __syncthreads();
    if (w == 0) {
        v = sh[lane & 7];
        #pragma unroll
        for (int o = 4; o; o >>= 1) {
            float u = __shfl_xor_sync(0xffffffffu, v, o);
            v = MAX ? fmaxf(v, u) : v + u;
        }
        if (lane == 0) sh[0] = v;
    }
    __syncthreads();
    float r = sh[0];
    __syncthreads();
    return r;
}

// ---------------- LayerNorm (fp32 in -> bf16 out) ----------------
__global__ void ln_kernel(const float* __restrict__ x, const float* __restrict__ g,
                          const float* __restrict__ beta, __nv_bfloat16* __restrict__ out) {
    size_t base = (size_t)blockIdx.x * HID_;
    const float4* xp = reinterpret_cast<const float4*>(x + base);
    int t = threadIdx.x;
    float4 v = xp[t];
    float s = v.x + v.y + v.z + v.w;
    s = block_reduce_256<false>(s);
    float mean = s * (1.0f / HID_);
    float dx = v.x - mean, dy = v.y - mean, dz = v.z - mean, dw = v.w - mean;
    float q = dx*dx + dy*dy + dz*dz + dw*dw;
    q = block_reduce_256<false>(q);
    float r = rsqrtf(q * (1.0f / HID_) + 1e-5f);
    float4 gv = reinterpret_cast<const float4*>(g)[t];
    float4 bv = reinterpret_cast<const float4*>(beta)[t];
    uint2 o;
    o.x = bf2(dx * r * gv.x + bv.x, dy * r * gv.y + bv.y);
    o.y = bf2(dz * r * gv.z + bv.z, dw * r * gv.w + bv.w);
    reinterpret_cast<uint2*>(out + base)[t] = o;
}

// ---------------- transpose V ----------------
__global__ void transpose_v_kernel(const __nv_bfloat16* __restrict__ qkv,
                                   __nv_bfloat16* __restrict__ vt) {
    __shared__ __nv_bfloat16 t[32][34];
    int bz = blockIdx.y;
    int b = bz / (NH_ * 2);
    int rem = bz % (NH_ * 2);
    int h = rem >> 1;
    int d0 = (rem & 1) * 32;
    int s0 = blockIdx.x * 32;
    int tx = threadIdx.x & 31, ty = threadIdx.x >> 5;
    #pragma unroll
    for (int i = 0; i < 32; i += 8)
        t[ty + i][tx] = qkv[((size_t)b * SS_ + s0 + ty + i) * QKVLD + 2 * HID_ + h * 64 + d0 + tx];
    __syncthreads();
    #pragma unroll
    for (int i = 0; i < 32; i += 8)
        vt[(((size_t)b * NH_ + h) * 64 + d0 + ty + i) * SS_ + s0 + tx] = t[tx][ty + i];
}

// ---------------- fused flash attention, no online max (scores bounded) ----------------
#define FFS 72
#define FQ  0
#define FK  (128*FFS)
#define FV  (FK + 2*64*FFS)
#define FP  (FV + 2*64*FFS)
#define FL_FLT ((FP + 128*FFS) * 2)
#define FL_SMEM (FL_FLT + (2048 + 512) * 4)

__global__ __launch_bounds__(256, 2) void flash_kernel(
    const __nv_bfloat16* __restrict__ qkv, const __nv_bfloat16* __restrict__ vt,
    const float* __restrict__ am, __nv_bfloat16* __restrict__ ctx)
{
    extern __shared__ __align__(16) char smc[];
    float* Madd = reinterpret_cast<float*>(smc + FL_FLT);
    float* Psum = Madd + 2048;

    const int tid = threadIdx.x, lane = tid & 31, wid = tid >> 5;
    const int wm = wid >> 2, wn = wid & 3;
    const int qq = lane >> 3, l8 = lane & 7;
    const int arow = ((qq & 1) << 3) + l8, acol = (qq >> 1) << 3;
    const int brow = ((qq >> 1) << 3) + l8, bcol = (qq & 1) << 3;
    const int qt = blockIdx.x, bh = blockIdx.y;
    const int bb = bh >> 4, hh = bh & 15;
    const int q0 = qt * 128;

    const __nv_bfloat16* Qg = qkv + ((size_t)bb * SS_ + q0) * QKVLD + hh * 64;
    const __nv_bfloat16* Kg = qkv + (size_t)bb * SS_ * QKVLD + HID_ + hh * 64;
    const __nv_bfloat16* Vg = vt + (size_t)bh * 64 * SS_;

    const uint32_t sb = smem_u32(smc);
    const uint32_t sQ = sb + FQ * 2, sP = sb + FP * 2;
    __nv_bfloat16* Ps = reinterpret_cast<__nv_bfloat16*>(smc) + FP;

    #pragma unroll
    for (int u = 0; u < 4; u++) {
        int idx = tid + u * 256;
        int r = idx >> 3, c8 = (idx & 7) << 3;
        CP16(sQ + (uint32_t)((r * FFS + c8) * 2), Qg + (size_t)r * QKVLD + c8);
    }
    CP_COMMIT();
    #pragma unroll
    for (int u = 0; u < 8; u++) {
        int i = tid + u * 256;
        Madd[i] = (__ldg(&am[(size_t)bb * SS_ + i]) - 1.0f) * 10000.0f;
    }

    auto load_kv = [&](int j, int s) {
        const int j0 = j * 64;
        uint32_t kb = sb + (uint32_t)((FK + s * 64 * FFS) * 2);
        uint32_t vb = sb + (uint32_t)((FV + s * 64 * FFS) * 2);
        #pragma unroll
        for (int u = 0; u < 2; u++) {
            int idx = tid + u * 256;
            int r = idx >> 3, c8 = (idx & 7) << 3;
            CP16(kb + (uint32_t)((r * FFS + c8) * 2), Kg + (size_t)(j0 + r) * QKVLD + c8);
        }
        #pragma unroll
        for (int u = 0; u < 2; u++) {
            int idx = tid + u * 256;
            int r = idx >> 3, c8 = (idx & 7) << 3;
            CP16(vb + (uint32_t)((r * FFS + c8) * 2), Vg + (size_t)r * SS_ + j0 + c8);
        }
        CP_COMMIT();
    };
    load_kv(0, 0);

    float ctxa[4][2][4] = {};
    float lrow[4][2] = {};

    const int IT = SS_ / 64;
    for (int j = 0; j < IT; j++) {
        const int s = j & 1;
        __syncthreads();
        if (j + 1 < IT) { load_kv(j + 1, s ^ 1); CP_WAIT1(); }
        else            { CP_WAIT0(); }
        __syncthreads();

        // ---- S = Q @ K^T ----
        float sacc[4][2][4] = {};
        const uint32_t sKs = sb + (uint32_t)((FK + s * 64 * FFS) * 2);
        #pragma unroll
        for (int kk = 0; kk < 4; kk++) {
            uint32_t af[4][4];
            #pragma unroll
            for (int mt = 0; mt < 4; mt++) {
                int rr = wm * 64 + mt * 16 + arow;
                LDSM4(af[mt][0], af[mt][1], af[mt][2], af[mt][3],
                      sQ + (uint32_t)((rr * FFS + kk * 16 + acol) * 2));
            }
            uint32_t b4[4];
            {
                int nn = wn * 16 + brow;
                LDSM4(b4[0], b4[1], b4[2], b4[3],
                      sKs + (uint32_t)((nn * FFS + kk * 16 + bcol) * 2));
            }
            #pragma unroll
            for (int mt = 0; mt < 4; mt++) {
                mma16816(sacc[mt][0], af[mt], b4[0], b4[1]);
                mma16816(sacc[mt][1], af[mt], b4[2], b4[3]);
            }
        }

        // ---- P = exp(s*0.125 + madd); local row sums; store P ----
        const int j0 = j * 64;
        float lsum[4][2] = {};
        #pragma unroll
        for (int nt = 0; nt < 2; nt++) {
            int cl = wn * 16 + nt * 8 + 2 * (lane & 3);
            float2 md = *reinterpret_cast<const float2*>(&Madd[j0 + cl]);
            #pragma unroll
            for (int mt = 0; mt < 4; mt++)
                #pragma unroll
                for (int h2 = 0; h2 < 2; h2++) {
                    float p0 = __expf(fmaf(sacc[mt][nt][2 * h2 + 0], 0.125f, md.x));
                    float p1 = __expf(fmaf(sacc[mt][nt][2 * h2 + 1], 0.125f, md.y));
                    lsum[mt][h2] += p0 + p1;
                    int row = wm * 64 + mt * 16 + h2 * 8 + (lane >> 2);
                    *reinterpret_cast<uint32_t*>(&Ps[row * FFS + cl]) = bf2(p0, p1);
                }
        }
        #pragma unroll
        for (int mt = 0; mt < 4; mt++)
            #pragma unroll
            for (int h2 = 0; h2 < 2; h2++) {
                float v = lsum[mt][h2];
                v += __shfl_xor_sync(0xffffffffu, v, 1);
                v += __shfl_xor_sync(0xffffffffu, v, 2);
                lsum[mt][h2] = v;
            }
        if ((lane & 3) == 0) {
            #pragma unroll
            for (int mt = 0; mt < 4; mt++)
                #pragma unroll
                for (int h2 = 0; h2 < 2; h2++) {
                    int row = wm * 64 + mt * 16 + h2 * 8 + (lane >> 2);
                    Psum[wn * 128 + row] = lsum[mt][h2];
                }
        }
        __syncthreads();           // Ps + Psum visible
        #pragma unroll
        for (int mt = 0; mt < 4; mt++)
            #pragma unroll
            for (int h2 = 0; h2 < 2; h2++) {
                int row = wm * 64 + mt * 16 + h2 * 8 + (lane >> 2);
                lrow[mt][h2] += Psum[row] + Psum[128 + row] + Psum[256 + row] + Psum[384 + row];
            }

        // ---- ctx += P @ V^T ----
        const uint32_t sVs = sb + (uint32_t)((FV + s * 64 * FFS) * 2);
        #pragma unroll
        for (int kk = 0; kk < 4; kk++) {
            uint32_t af[4][4];
            #pragma unroll
            for (int mt = 0; mt < 4; mt++) {
                int rr = wm * 64 + mt * 16 + arow;
                LDSM4(af[mt][0], af[mt][1], af[mt][2], af[mt][3],
                      sP + (uint32_t)((rr * FFS + kk * 16 + acol) * 2));
            }
            uint32_t b4[4];
            {
                int nn = wn * 16 + brow;
                LDSM4(b4[0], b4[1], b4[2], b4[3],
                      sVs + (uint32_t)((nn * FFS + kk * 16 + bcol) * 2));
            }
            #pragma unroll
            for (int mt = 0; mt < 4; mt++) {
                mma16816(ctxa[mt][0], af[mt], b4[0], b4[1]);
                mma16816(ctxa[mt][1], af[mt], b4[2], b4[3]);
            }
        }
    }

    #pragma unroll
    for (int mt = 0; mt < 4; mt++)
        #pragma unroll
        for (int h2 = 0; h2 < 2; h2++) {
            int row = wm * 64 + mt * 16 + h2 * 8 + (lane >> 2);
            float inv = 1.0f / lrow[mt][h2];
            #pragma unroll
            for (int nt = 0; nt < 2; nt++) {
                int cl = wn * 16 + nt * 8 + 2 * (lane & 3);
                *reinterpret_cast<uint32_t*>(
                    ctx + ((size_t)bb * SS_ + q0 + row) * HID_ + hh * 64 + cl) =
                    bf2(ctxa[mt][nt][2 * h2 + 0] * inv, ctxa[mt][nt][2 * h2 + 1] * inv);
            }
        }
}

// ---------------- bf16 mma GEMM (R10 proven config) ----------------
// EPI: 0 = +bias -> bf16; 2 = gelu(+bias) -> bf16; 3 = +bias+residual -> fp32
template<int EPI>
__global__ __launch_bounds__(256, 2) void tc_gemm(
    int M, int N, int K,
    const __nv_bfloat16* __restrict__ A,  int lda,
    const __nv_bfloat16* __restrict__ Bm, int ldb,
    float* __restrict__ Cf, __nv_bfloat16* __restrict__ Cb, int ldc,
    const float* __restrict__ bias, const float* __restrict__ residual)
{
    constexpr int RS  = 72;
    constexpr int ASZ = 128 * RS;
    constexpr int STG = 2 * ASZ;
    constexpr int NT  = 4;

    extern __shared__ __align__(16) char smc[];

    const int tid  = threadIdx.x;
    const int wid  = tid >> 5, lane = tid & 31;
    const int wm   = wid >> 2, wn = wid & 3;
    const int qq   = lane >> 3, l8 = lane & 7;
    const int arow = ((qq & 1) << 3) + l8, acol = (qq >> 1) << 3;
    const int brow = ((qq >> 1) << 3) + l8, bcol = (qq & 1) << 3;
    const int row0 = blockIdx.y * 128;
    const int col0 = blockIdx.x * 128;

    const uint32_t sbase = smem_u32(smc);

    float acc[4][NT][4];
    #pragma unroll
    for (int i = 0; i < 4; i++)
        #pragma unroll
        for (int j = 0; j < NT; j++)
            #pragma unroll
            for (int e = 0; e < 4; e++) acc[i][j][e] = 0.0f;

    const int nk = K >> 6;

    auto load_stage = [&](int i, int s) {
        const int k0 = i << 6;
        uint32_t abase = sbase + (uint32_t)(s * STG) * 2u;
        uint32_t bbase = abase + (uint32_t)ASZ * 2u;
        #pragma unroll
        for (int u = 0; u < 4; u++) {
            int idx = tid + u * 256;
            int r = idx >> 3, c8 = (idx & 7) << 3;
            CP16(abase + (uint32_t)(r * RS + c8) * 2u,
                 A + (size_t)(row0 + r) * lda + k0 + c8);
        }
        #pragma unroll
        for (int u = 0; u < 4; u++) {
            int idx = tid + u * 256;
            int r = idx >> 3, c8 = (idx & 7) << 3;
            CP16(bbase + (uint32_t)(r * RS + c8) * 2u,
                 Bm + (size_t)(col0 + r) * ldb + k0 + c8);
        }
        CP_COMMIT();
    };

    load_stage(0, 0);
    load_stage(1, 1);

    int s = 0;
    for (int i = 0; i < nk; i++) {
        if (i == nk - 1) { CP_WAIT0(); } else { CP_WAIT1(); }
        __syncthreads();
        int ns = s + 2; if (ns >= 3) ns -= 3;
        if (i + 2 < nk) load_stage(i + 2, ns);

        const uint32_t sAs = sbase + (uint32_t)(s * STG) * 2u;
        const uint32_t sBs = sAs + (uint32_t)ASZ * 2u;

        #pragma unroll
        for (int kk = 0; kk < 4; kk++) {
            uint32_t af[4][4];
            #pragma unroll
            for (int mt = 0; mt < 4; mt++) {
                int rr = wm * 64 + mt * 16 + arow;
                LDSM4(af[mt][0], af[mt][1], af[mt][2], af[mt][3],
                      sAs + (uint32_t)((rr * RS + kk * 16 + acol) * 2));
            }
            uint32_t bf[NT][2];
            #pragma unroll
            for (int ntp = 0; ntp < NT / 2; ntp++) {
                int nn = wn * 32 + ntp * 16 + brow;
                LDSM4(bf[2*ntp][0], bf[2*ntp][1], bf[2*ntp+1][0], bf[2*ntp+1][1],
                      sBs + (uint32_t)((nn * RS + kk * 16 + bcol) * 2));
            }
            #pragma unroll
            for (int nt = 0; nt < NT; nt++)
                #pragma unroll
                for (int mt = 0; mt < 4; mt++)
                    mma16816(acc[mt][nt], af[mt], bf[nt][0], bf[nt][1]);
        }
        s++; if (s == 3) s = 0;
    }

    #pragma unroll
    for (int mt = 0; mt < 4; mt++) {
        #pragma unroll
        for (int nt = 0; nt < NT; nt++) {
            int r0 = row0 + wm * 64 + mt * 16 + (lane >> 2);
            int c0 = col0 + wn * 32 + nt * 8 + 2 * (lane & 3);
            #pragma unroll
            for (int half = 0; half < 2; half++) {
                int r = r0 + half * 8;
                float v0 = acc[mt][nt][2 * half + 0];
                float v1 = acc[mt][nt][2 * half + 1];
                v0 += __ldg(&bias[c0]);
                v1 += __ldg(&bias[c0 + 1]);
                if (EPI == 2) {
                    v0 = 0.5f * v0 * (1.0f + erff(v0 * 0.70710678118654752f));
                    v1 = 0.5f * v1 * (1.0f + erff(v1 * 0.70710678118654752f));
                }
                if (EPI == 3) {
                    float2 rr = *reinterpret_cast<const float2*>(
                        residual + (size_t)r * ldc + c0);
                    v0 += rr.x; v1 += rr.y;
                    float2 o; o.x = v0; o.y = v1;
                    *reinterpret_cast<float2*>(Cf + (size_t)r * ldc + c0) = o;
                } else {
                    *reinterpret_cast<uint32_t*>(Cb + (size_t)r * ldc + c0) = bf2(v0, v1);
                }
            }
        }
    }
}

// ---------------- launch ----------------
extern "C" void kernel_launch(void* const* d_in, const int* in_sizes, int n_in,
                              void* d_out, int out_size) {
    const float* x   = (const float*)d_in[0];
    const float* am  = (const float*)d_in[1];
    const float* Wq  = (const float*)d_in[2];
    const float* bq  = (const float*)d_in[3];
    const float* Wk  = (const float*)d_in[4];
    const float* bk  = (const float*)d_in[5];
    const float* Wv  = (const float*)d_in[6];
    const float* bv  = (const float*)d_in[7];
    const float* Wo  = (const float*)d_in[8];
    const float* bo  = (const float*)d_in[9];
    const float* W1  = (const float*)d_in[10];
    const float* b1  = (const float*)d_in[11];
    const float* W2  = (const float*)d_in[12];
    const float* b2  = (const float*)d_in[13];
    const float* g1  = (const float*)d_in[14];
    const float* be1 = (const float*)d_in[15];
    const float* g2  = (const float*)d_in[16];
    const float* be2 = (const float*)d_in[17];
    float* out = (float*)d_out;

    __nv_bfloat16 *h, *qkv, *vt, *ctx, *h2, *ff, *wb;
    float *x2, *bqkv;
    cudaGetSymbolAddress((void**)&h,    g_h);
    cudaGetSymbolAddress((void**)&qkv,  g_qkv);
    cudaGetSymbolAddress((void**)&vt,   g_vt);
    cudaGetSymbolAddress((void**)&ctx,  g_ctx);
    cudaGetSymbolAddress((void**)&x2,   g_x2);
    cudaGetSymbolAddress((void**)&h2,   g_h2);
    cudaGetSymbolAddress((void**)&ff,   g_ff);
    cudaGetSymbolAddress((void**)&wb,   g_wb);
    cudaGetSymbolAddress((void**)&bqkv, g_bqkv);

    __nv_bfloat16* rWqkv = wb;
    __nv_bfloat16* rWo = wb + 3 * 1024 * 1024;
    __nv_bfloat16* rW1 = wb + 4 * 1024 * 1024;
    __nv_bfloat16* rW2 = wb + 8 * 1024 * 1024;

    const int SM3 = 3 * 2 * 128 * 72 * 2;            // 110592 bytes
    cudaFuncSetAttribute(tc_gemm<0>, cudaFuncAttributeMaxDynamicSharedMemorySize, SM3);
    cudaFuncSetAttribute(tc_gemm<2>, cudaFuncAttributeMaxDynamicSharedMemorySize, SM3);
    cudaFuncSetAttribute(tc_gemm<3>, cudaFuncAttributeMaxDynamicSharedMemorySize, SM3);
    cudaFuncSetAttribute(flash_kernel, cudaFuncAttributeMaxDynamicSharedMemorySize, FL_SMEM);

    dim3 blk(256);

    pack_bias_kernel<<<12, blk>>>(bq, bk, bv, bqkv);
    round4_kernel<<<4096, blk>>>(Wq, Wk, Wv, Wo, rWqkv, rWqkv + 1024*1024,
                                 rWqkv + 2*1024*1024, rWo);
    ln_kernel<<<TOK_, blk>>>(x, g1, be1, h);
    tc_gemm<0><<<dim3(QKVLD/128, TOK_/128), blk, SM3>>>(TOK_, QKVLD, HID_,
        h, HID_,  rWqkv, HID_,  nullptr, qkv, QKVLD,  bqkv, nullptr);
    transpose_v_kernel<<<dim3(SS_/32, BB_*NH_*2), blk>>>(qkv, vt);
    flash_kernel<<<dim3(SS_/128, BB_*NH_), blk, FL_SMEM>>>(qkv, vt, am, ctx);
    round2_kernel<<<8192, blk>>>(W1, W2, rW1, rW2);
    tc_gemm<3><<<dim3(HID_/128, TOK_/128), blk, SM3>>>(TOK_, HID_, HID_,
        ctx, HID_,  rWo, HID_,  x2, nullptr, HID_,  bo, x);
    ln_kernel<<<TOK_, blk>>>(x2, g2, be2, h2);
    tc_gemm<2><<<dim3(FF_/128, TOK_/128), blk, SM3>>>(TOK_, FF_, HID_,
        h2, HID_,  rW1, HID_,  nullptr, ff, FF_,  b1, nullptr);
    tc_gemm<3><<<dim3(HID_/128, TOK_/128), blk, SM3>>>(TOK_, HID_, FF_,
        ff, FF_,  rW2, FF_,  out, nullptr, HID_,  b2, x2);
}

// round 12
// speedup vs baseline: 1.1719x; 1.0160x over previous
#include <cuda_runtime.h>
#include <cuda_bf16.h>
#include <math.h>
#include <stdint.h>

#define BB_   2
#define SS_   2048
#define HID_  1024
#define NH_   16
#define HD_   64
#define FF_   4096
#define TOK_  (BB_*SS_)   // 4096
#define QKVLD 3072

// ---------------- scratch ----------------
__device__ __nv_bfloat16 g_h  [TOK_*HID_];
__device__ __nv_bfloat16 g_qkv[TOK_*3*HID_];       // [TOK, 3072] = q|k|v
__device__ __nv_bfloat16 g_ctx[TOK_*HID_];
__device__ float         g_x2 [TOK_*HID_];
__device__ __nv_bfloat16 g_h2 [TOK_*HID_];
__device__ __nv_bfloat16 g_ff [TOK_*FF_];
__device__ __nv_bfloat16 g_wb [12*1024*1024];      // bf16 weights (q|k|v|o|W1|W2)
__device__ float         g_bqkv[3*HID_];

// ---------------- helpers ----------------
__device__ __forceinline__ uint32_t bf2(float x, float y) {
    __nv_bfloat162 t = __floats2bfloat162_rn(x, y);
    return *reinterpret_cast<uint32_t*>(&t);
}
__device__ __forceinline__ uint32_t smem_u32(const void* p) {
    uint32_t a;
    asm("{ .reg .u64 t; cvta.to.shared.u64 t, %1; cvt.u32.u64 %0, t; }" : "=r"(a) : "l"(p));
    return a;
}
#define CP16(dst, src) \
    asm volatile("cp.async.cg.shared.global [%0], [%1], 16;" :: "r"(dst), "l"(src) : "memory")
#define CP_COMMIT() asm volatile("cp.async.commit_group;" ::: "memory")
#define CP_WAIT1()  asm volatile("cp.async.wait_group 1;" ::: "memory")
#define CP_WAIT0()  asm volatile("cp.async.wait_group 0;" ::: "memory")

#define LDSM4(R0, R1, R2, R3, ADDR) \
    asm volatile("ldmatrix.sync.aligned.m8n8.x4.shared.b16 {%0,%1,%2,%3}, [%4];" \
        : "=r"(R0), "=r"(R1), "=r"(R2), "=r"(R3) : "r"(ADDR))
#define LDSM4T(R0, R1, R2, R3, ADDR) \
    asm volatile("ldmatrix.sync.aligned.m8n8.x4.trans.shared.b16 {%0,%1,%2,%3}, [%4];" \
        : "=r"(R0), "=r"(R1), "=r"(R2), "=r"(R3) : "r"(ADDR))

__device__ __forceinline__ void mma16816(float* c, const uint32_t* a, uint32_t b0, uint32_t b1) {
    asm volatile(
        "mma.sync.aligned.m16n8k16.row.col.f32.bf16.bf16.f32 "
        "{%0,%1,%2,%3}, {%4,%5,%6,%7}, {%8,%9}, {%0,%1,%2,%3};"
        : "+f"(c[0]), "+f"(c[1]), "+f"(c[2]), "+f"(c[3])
        : "r"(a[0]), "r"(a[1]), "r"(a[2]), "r"(a[3]), "r"(b0), "r"(b1));
}

// ---------------- fused conversion: weights -> bf16 + bias pack, one launch ----------------
// blocks [0, 4096)    : Wq|Wk|Wv|Wo  (4 x 1M floats, float4-wise)
// blocks [4096, 12288): W1|W2        (2 x 4M floats)
// blocks [12288,12300): qkv bias pack
__global__ void convert_all_kernel(
    const float* __restrict__ Wq, const float* __restrict__ Wk,
    const float* __restrict__ Wv, const float* __restrict__ Wo,
    const float* __restrict__ W1, const float* __restrict__ W2,
    const float* __restrict__ bq, const float* __restrict__ bk,
    const float* __restrict__ bv,
    __nv_bfloat16* __restrict__ wb, float* __restrict__ bqkv)
{
    int bid = blockIdx.x;
    if (bid < 4096) {
        int i = bid * 256 + threadIdx.x;         // float4 index over 4x1M
        int seg = i >> 18, off = i & 262143;
        const float4* sp;
        __nv_bfloat16* dp;
        if      (seg == 0) { sp = (const float4*)Wq; dp = wb; }
        else if (seg == 1) { sp = (const float4*)Wk; dp = wb + 1024*1024; }
        else if (seg == 2) { sp = (const float4*)Wv; dp = wb + 2*1024*1024; }
        else               { sp = (const float4*)Wo; dp = wb + 3*1024*1024; }
        float4 v = sp[off];
        reinterpret_cast<uint2*>(dp)[off] = make_uint2(bf2(v.x, v.y), bf2(v.z, v.w));
    } else if (bid < 12288) {
        int i = (bid - 4096) * 256 + threadIdx.x;  // float4 index over 2x4M
        int seg = i >> 20, off = i & 1048575;
        const float4* sp = seg ? (const float4*)W2 : (const float4*)W1;
        __nv_bfloat16* dp = seg ? (wb + 8*1024*1024) : (wb + 4*1024*1024);
        float4 v = sp[off];
        reinterpret_cast<uint2*>(dp)[off] = make_uint2(bf2(v.x, v.y), bf2(v.z, v.w));
    } else {
        int i = (bid - 12288) * 256 + threadIdx.x;
        if (i < HID_)            bqkv[i] = bq[i];
        else if (i < 2 * HID_)   bqkv[i] = bk[i - HID_];
        else if (i < 3 * HID_)   bqkv[i] = bv[i - 2 * HID_];
    }
}

// ---------------- block reduction ----------------
template<bool MAX>
__device__ __forceinline__ float block_reduce_256(float v) {
    __shared__ float sh[8];
    int lane = threadIdx.x & 31, w = threadIdx.x >> 5;
    #pragma unroll
    for (int o = 16; o; o >>= 1) {
        float u = __shfl_xor_sync(0xffffffffu, v, o);
        v = MAX ? fmaxf(v, u) : v + u;
    }
    if (lane == 0) sh[w] = v;
    __syncthreads();
    if (w == 0) {
        v = sh[lane & 7];
        #pragma unroll
        for (int o = 4; o; o >>= 1) {
            float u = __shfl_xor_sync(0xffffffffu, v, o);
            v = MAX ? fmaxf(v, u) : v + u;
        }
        if (lane == 0) sh[0] = v;
    }
    __syncthreads();
    float r = sh[0];
    __syncthreads();
    return r;
}

// ---------------- LayerNorm (fp32 in -> bf16 out) ----------------
__global__ void ln_kernel(const float* __restrict__ x, const float* __restrict__ g,
                          const float* __restrict__ beta, __nv_bfloat16* __restrict__ out) {
    size_t base = (size_t)blockIdx.x * HID_;
    const float4* xp = reinterpret_cast<const float4*>(x + base);
    int t = threadIdx.x;
    float4 v = xp[t];
    float s = v.x + v.y + v.z + v.w;
    s = block_reduce_256<false>(s);
    float mean = s * (1.0f / HID_);
    float dx = v.x - mean, dy = v.y - mean, dz = v.z - mean, dw = v.w - mean;
    float q = dx*dx + dy*dy + dz*dz + dw*dw;
    q = block_reduce_256<false>(q);
    float r = rsqrtf(q * (1.0f / HID_) + 1e-5f);
    float4 gv = reinterpret_cast<const float4*>(g)[t];
    float4 bv = reinterpret_cast<const float4*>(beta)[t];
    uint2 o;
    o.x = bf2(dx * r * gv.x + bv.x, dy * r * gv.y + bv.y);
    o.y = bf2(dz * r * gv.z + bv.z, dw * r * gv.w + bv.w);
    reinterpret_cast<uint2*>(out + base)[t] = o;
}

// ---------------- fused flash attention: no online max, V via ldmatrix.trans ----------------
#define FFS 72
#define FQ  0
#define FK  (128*FFS)
#define FV  (FK + 2*64*FFS)
#define FP  (FV + 2*64*FFS)
#define FL_FLT ((FP + 128*FFS) * 2)
#define FL_SMEM (FL_FLT + (2048 + 512) * 4)

__global__ __launch_bounds__(256, 2) void flash_kernel(
    const __nv_bfloat16* __restrict__ qkv,
    const float* __restrict__ am, __nv_bfloat16* __restrict__ ctx)
{
    extern __shared__ __align__(16) char smc[];
    float* Madd = reinterpret_cast<float*>(smc + FL_FLT);
    float* Psum = Madd + 2048;

    const int tid = threadIdx.x, lane = tid & 31, wid = tid >> 5;
    const int wm = wid >> 2, wn = wid & 3;
    const int qq = lane >> 3, l8 = lane & 7;
    const int arow = ((qq & 1) << 3) + l8, acol = (qq >> 1) << 3;
    const int brow = ((qq >> 1) << 3) + l8, bcol = (qq & 1) << 3;
    // trans-B pattern (V token-major): row = k(token), col = n(dh)
    const int tkrow = ((qq & 1) << 3) + l8, tncol = (qq >> 1) << 3;
    const int qt = blockIdx.x, bh = blockIdx.y;
    const int bb = bh >> 4, hh = bh & 15;
    const int q0 = qt * 128;

    const __nv_bfloat16* Qg = qkv + ((size_t)bb * SS_ + q0) * QKVLD + hh * 64;
    const __nv_bfloat16* Kg = qkv + (size_t)bb * SS_ * QKVLD + HID_ + hh * 64;
    const __nv_bfloat16* Vg = qkv + (size_t)bb * SS_ * QKVLD + 2 * HID_ + hh * 64;

    const uint32_t sb = smem_u32(smc);
    const uint32_t sQ = sb + FQ * 2, sP = sb + FP * 2;
    __nv_bfloat16* Ps = reinterpret_cast<__nv_bfloat16*>(smc) + FP;

    #pragma unroll
    for (int u = 0; u < 4; u++) {
        int idx = tid + u * 256;
        int r = idx >> 3, c8 = (idx & 7) << 3;
        CP16(sQ + (uint32_t)((r * FFS + c8) * 2), Qg + (size_t)r * QKVLD + c8);
    }
    CP_COMMIT();
    #pragma unroll
    for (int u = 0; u < 8; u++) {
        int i = tid + u * 256;
        Madd[i] = (__ldg(&am[(size_t)bb * SS_ + i]) - 1.0f) * 10000.0f;
    }

    auto load_kv = [&](int j, int s) {
        const int j0 = j * 64;
        uint32_t kb = sb + (uint32_t)((FK + s * 64 * FFS) * 2);
        uint32_t vb = sb + (uint32_t)((FV + s * 64 * FFS) * 2);
        #pragma unroll
        for (int u = 0; u < 2; u++) {
            int idx = tid + u * 256;
            int r = idx >> 3, c8 = (idx & 7) << 3;
            CP16(kb + (uint32_t)((r * FFS + c8) * 2), Kg + (size_t)(j0 + r) * QKVLD + c8);
        }
        #pragma unroll
        for (int u = 0; u < 2; u++) {
            int idx = tid + u * 256;
            int r = idx >> 3, c8 = (idx & 7) << 3;   // r = token row, c8 = dh col
            CP16(vb + (uint32_t)((r * FFS + c8) * 2), Vg + (size_t)(j0 + r) * QKVLD + c8);
        }
        CP_COMMIT();
    };
    load_kv(0, 0);

    float ctxa[4][2][4] = {};
    float lrow[4][2] = {};

    const int IT = SS_ / 64;
    for (int j = 0; j < IT; j++) {
        const int s = j & 1;
        __syncthreads();
        if (j + 1 < IT) { load_kv(j + 1, s ^ 1); CP_WAIT1(); }
        else            { CP_WAIT0(); }
        __syncthreads();

        // ---- S = Q @ K^T ----
        float sacc[4][2][4] = {};
        const uint32_t sKs = sb + (uint32_t)((FK + s * 64 * FFS) * 2);
        #pragma unroll
        for (int kk = 0; kk < 4; kk++) {
            uint32_t af[4][4];
            #pragma unroll
            for (int mt = 0; mt < 4; mt++) {
                int rr = wm * 64 + mt * 16 + arow;
                LDSM4(af[mt][0], af[mt][1], af[mt][2], af[mt][3],
                      sQ + (uint32_t)((rr * FFS + kk * 16 + acol) * 2));
            }
            uint32_t b4[4];
            {
                int nn = wn * 16 + brow;
                LDSM4(b4[0], b4[1], b4[2], b4[3],
                      sKs + (uint32_t)((nn * FFS + kk * 16 + bcol) * 2));
            }
            #pragma unroll
            for (int mt = 0; mt < 4; mt++) {
                mma16816(sacc[mt][0], af[mt], b4[0], b4[1]);
                mma16816(sacc[mt][1], af[mt], b4[2], b4[3]);
            }
        }

        // ---- P = exp(s*0.125 + madd); row sums; store P ----
        const int j0 = j * 64;
        float lsum[4][2] = {};
        #pragma unroll
        for (int nt = 0; nt < 2; nt++) {
            int cl = wn * 16 + nt * 8 + 2 * (lane & 3);
            float2 md = *reinterpret_cast<const float2*>(&Madd[j0 + cl]);
            #pragma unroll
            for (int mt = 0; mt < 4; mt++)
                #pragma unroll
                for (int h2 = 0; h2 < 2; h2++) {
                    float p0 = __expf(fmaf(sacc[mt][nt][2 * h2 + 0], 0.125f, md.x));
                    float p1 = __expf(fmaf(sacc[mt][nt][2 * h2 + 1], 0.125f, md.y));
                    lsum[mt][h2] += p0 + p1;
                    int row = wm * 64 + mt * 16 + h2 * 8 + (lane >> 2);
                    *reinterpret_cast<uint32_t*>(&Ps[row * FFS + cl]) = bf2(p0, p1);
                }
        }
        #pragma unroll
        for (int mt = 0; mt < 4; mt++)
            #pragma unroll
            for (int h2 = 0; h2 < 2; h2++) {
                float v = lsum[mt][h2];
                v += __shfl_xor_sync(0xffffffffu, v, 1);
                v += __shfl_xor_sync(0xffffffffu, v, 2);
                lsum[mt][h2] = v;
            }
        if ((lane & 3) == 0) {
            #pragma unroll
            for (int mt = 0; mt < 4; mt++)
                #pragma unroll
                for (int h2 = 0; h2 < 2; h2++) {
                    int row = wm * 64 + mt * 16 + h2 * 8 + (lane >> 2);
                    Psum[wn * 128 + row] = lsum[mt][h2];
                }
        }
        __syncthreads();
        #pragma unroll
        for (int mt = 0; mt < 4; mt++)
            #pragma unroll
            for (int h2 = 0; h2 < 2; h2++) {
                int row = wm * 64 + mt * 16 + h2 * 8 + (lane >> 2);
                lrow[mt][h2] += Psum[row] + Psum[128 + row] + Psum[256 + row] + Psum[384 + row];
            }

        // ---- ctx += P @ V  (V token-major; B frags via ldmatrix.trans) ----
        const uint32_t sVs = sb + (uint32_t)((FV + s * 64 * FFS) * 2);
        #pragma unroll
        for (int kk = 0; kk < 4; kk++) {
            uint32_t af[4][4];
            #pragma unroll
            for (int mt = 0; mt < 4; mt++) {
                int rr = wm * 64 + mt * 16 + arow;
                LDSM4(af[mt][0], af[mt][1], af[mt][2], af[mt][3],
                      sP + (uint32_t)((rr * FFS + kk * 16 + acol) * 2));
            }
            uint32_t b4[4];
            {
                int kr = kk * 16 + tkrow;            // token (k) row
                int nc = wn * 16 + tncol;            // dh (n) col
                LDSM4T(b4[0], b4[1], b4[2], b4[3],
                       sVs + (uint32_t)((kr * FFS + nc) * 2));
            }
            #pragma unroll
            for (int mt = 0; mt < 4; mt++) {
                mma16816(ctxa[mt][0], af[mt], b4[0], b4[1]);
                mma16816(ctxa[mt][1], af[mt], b4[2], b4[3]);
            }
        }
    }

    #pragma unroll
    for (int mt = 0; mt < 4; mt++)
        #pragma unroll
        for (int h2 = 0; h2 < 2; h2++) {
            int row = wm * 64 + mt * 16 + h2 * 8 + (lane >> 2);
            float inv = 1.0f / lrow[mt][h2];
            #pragma unroll
            for (int nt = 0; nt < 2; nt++) {
                int cl = wn * 16 + nt * 8 + 2 * (lane & 3);
                *reinterpret_cast<uint32_t*>(
                    ctx + ((size_t)bb * SS_ + q0 + row) * HID_ + hh * 64 + cl) =
                    bf2(ctxa[mt][nt][2 * h2 + 0] * inv, ctxa[mt][nt][2 * h2 + 1] * inv);
            }
        }
}

// ---------------- bf16 mma GEMM (R10 proven config) ----------------
// EPI: 0 = +bias -> bf16; 2 = gelu(+bias) -> bf16; 3 = +bias+residual -> fp32
template<int EPI>
__global__ __launch_bounds__(256, 2) void tc_gemm(
    int M, int N, int K,
    const __nv_bfloat16* __restrict__ A,  int lda,
    const __nv_bfloat16* __restrict__ Bm, int ldb,
    float* __restrict__ Cf, __nv_bfloat16* __restrict__ Cb, int ldc,
    const float* __restrict__ bias, const float* __restrict__ residual)
{
    constexpr int RS  = 72;
    constexpr int ASZ = 128 * RS;
    constexpr int STG = 2 * ASZ;
    constexpr int NT  = 4;

    extern __shared__ __align__(16) char smc[];

    const int tid  = threadIdx.x;
    const int wid  = tid >> 5, lane = tid & 31;
    const int wm   = wid >> 2, wn = wid & 3;
    const int qq   = lane >> 3, l8 = lane & 7;
    const int arow = ((qq & 1) << 3) + l8, acol = (qq >> 1) << 3;
    const int brow = ((qq >> 1) << 3) + l8, bcol = (qq & 1) << 3;
    const int row0 = blockIdx.y * 128;
    const int col0 = blockIdx.x * 128;

    const uint32_t sbase = smem_u32(smc);

    float acc[4][NT][4];
    #pragma unroll
    for (int i = 0; i < 4; i++)
        #pragma unroll
        for (int j = 0; j < NT; j++)
            #pragma unroll
            for (int e = 0; e < 4; e++) acc[i][j][e] = 0.0f;

    const int nk = K >> 6;

    auto load_stage = [&](int i, int s) {
        const int k0 = i << 6;
        uint32_t abase = sbase + (uint32_t)(s * STG) * 2u;
        uint32_t bbase = abase + (uint32_t)ASZ * 2u;
        #pragma unroll
        for (int u = 0; u < 4; u++) {
            int idx = tid + u * 256;
            int r = idx >> 3, c8 = (idx & 7) << 3;
            CP16(abase + (uint32_t)(r * RS + c8) * 2u,
                 A + (size_t)(row0 + r) * lda + k0 + c8);
        }
        #pragma unroll
        for (int u = 0; u < 4; u++) {
            int idx = tid + u * 256;
            int r = idx >> 3, c8 = (idx & 7) << 3;
            CP16(bbase + (uint32_t)(r * RS + c8) * 2u,
                 Bm + (size_t)(col0 + r) * ldb + k0 + c8);
        }
        CP_COMMIT();
    };

    load_stage(0, 0);
    load_stage(1, 1);

    int s = 0;
    for (int i = 0; i < nk; i++) {
        if (i == nk - 1) { CP_WAIT0(); } else { CP_WAIT1(); }
        __syncthreads();
        int ns = s + 2; if (ns >= 3) ns -= 3;
        if (i + 2 < nk) load_stage(i + 2, ns);

        const uint32_t sAs = sbase + (uint32_t)(s * STG) * 2u;
        const uint32_t sBs = sAs + (uint32_t)ASZ * 2u;

        #pragma unroll
        for (int kk = 0; kk < 4; kk++) {
            uint32_t af[4][4];
            #pragma unroll
            for (int mt = 0; mt < 4; mt++) {
                int rr = wm * 64 + mt * 16 + arow;
                LDSM4(af[mt][0], af[mt][1], af[mt][2], af[mt][3],
                      sAs + (uint32_t)((rr * RS + kk * 16 + acol) * 2));
            }
            uint32_t bf[NT][2];
            #pragma unroll
            for (int ntp = 0; ntp < NT / 2; ntp++) {
                int nn = wn * 32 + ntp * 16 + brow;
                LDSM4(bf[2*ntp][0], bf[2*ntp][1], bf[2*ntp+1][0], bf[2*ntp+1][1],
                      sBs + (uint32_t)((nn * RS + kk * 16 + bcol) * 2));
            }
            #pragma unroll
            for (int nt = 0; nt < NT; nt++)
                #pragma unroll
                for (int mt = 0; mt < 4; mt++)
                    mma16816(acc[mt][nt], af[mt], bf[nt][0], bf[nt][1]);
        }
        s++; if (s == 3) s = 0;
    }

    #pragma unroll
    for (int mt = 0; mt < 4; mt++) {
        #pragma unroll
        for (int nt = 0; nt < NT; nt++) {
            int r0 = row0 + wm * 64 + mt * 16 + (lane >> 2);
            int c0 = col0 + wn * 32 + nt * 8 + 2 * (lane & 3);
            #pragma unroll
            for (int half = 0; half < 2; half++) {
                int r = r0 + half * 8;
                float v0 = acc[mt][nt][2 * half + 0];
                float v1 = acc[mt][nt][2 * half + 1];
                v0 += __ldg(&bias[c0]);
                v1 += __ldg(&bias[c0 + 1]);
                if (EPI == 2) {
                    v0 = 0.5f * v0 * (1.0f + erff(v0 * 0.70710678118654752f));
                    v1 = 0.5f * v1 * (1.0f + erff(v1 * 0.70710678118654752f));
                }
                if (EPI == 3) {
                    float2 rr = *reinterpret_cast<const float2*>(
                        residual + (size_t)r * ldc + c0);
                    v0 += rr.x; v1 += rr.y;
                    float2 o; o.x = v0; o.y = v1;
                    *reinterpret_cast<float2*>(Cf + (size_t)r * ldc + c0) = o;
                } else {
                    *reinterpret_cast<uint32_t*>(Cb + (size_t)r * ldc + c0) = bf2(v0, v1);
                }
            }
        }
    }
}

// ---------------- launch ----------------
extern "C" void kernel_launch(void* const* d_in, const int* in_sizes, int n_in,
                              void* d_out, int out_size) {
    const float* x   = (const float*)d_in[0];
    const float* am  = (const float*)d_in[1];
    const float* Wq  = (const float*)d_in[2];
    const float* bq  = (const float*)d_in[3];
    const float* Wk  = (const float*)d_in[4];
    const float* bk  = (const float*)d_in[5];
    const float* Wv  = (const float*)d_in[6];
    const float* bv  = (const float*)d_in[7];
    const float* Wo  = (const float*)d_in[8];
    const float* bo  = (const float*)d_in[9];
    const float* W1  = (const float*)d_in[10];
    const float* b1  = (const float*)d_in[11];
    const float* W2  = (const float*)d_in[12];
    const float* b2  = (const float*)d_in[13];
    const float* g1  = (const float*)d_in[14];
    const float* be1 = (const float*)d_in[15];
    const float* g2  = (const float*)d_in[16];
    const float* be2 = (const float*)d_in[17];
    float* out = (float*)d_out;

    __nv_bfloat16 *h, *qkv, *ctx, *h2, *ff, *wb;
    float *x2, *bqkv;
    cudaGetSymbolAddress((void**)&h,    g_h);
    cudaGetSymbolAddress((void**)&qkv,  g_qkv);
    cudaGetSymbolAddress((void**)&ctx,  g_ctx);
    cudaGetSymbolAddress((void**)&x2,   g_x2);
    cudaGetSymbolAddress((void**)&h2,   g_h2);
    cudaGetSymbolAddress((void**)&ff,   g_ff);
    cudaGetSymbolAddress((void**)&wb,   g_wb);
    cudaGetSymbolAddress((void**)&bqkv, g_bqkv);

    __nv_bfloat16* rWqkv = wb;
    __nv_bfloat16* rWo = wb + 3 * 1024 * 1024;
    __nv_bfloat16* rW1 = wb + 4 * 1024 * 1024;
    __nv_bfloat16* rW2 = wb + 8 * 1024 * 1024;

    const int SM3 = 3 * 2 * 128 * 72 * 2;            // 110592 bytes
    cudaFuncSetAttribute(tc_gemm<0>, cudaFuncAttributeMaxDynamicSharedMemorySize, SM3);
    cudaFuncSetAttribute(tc_gemm<2>, cudaFuncAttributeMaxDynamicSharedMemorySize, SM3);
    cudaFuncSetAttribute(tc_gemm<3>, cudaFuncAttributeMaxDynamicSharedMemorySize, SM3);
    cudaFuncSetAttribute(flash_kernel, cudaFuncAttributeMaxDynamicSharedMemorySize, FL_SMEM);

    dim3 blk(256);

    // 0: all weight conversion + bias pack in one launch
    convert_all_kernel<<<12300, blk>>>(Wq, Wk, Wv, Wo, W1, W2, bq, bk, bv, wb, bqkv);
    // 1: h = LN1(x)
    ln_kernel<<<TOK_, blk>>>(x, g1, be1, h);
    // 2: qkv
    tc_gemm<0><<<dim3(QKVLD/128, TOK_/128), blk, SM3>>>(TOK_, QKVLD, HID_,
        h, HID_,  rWqkv, HID_,  nullptr, qkv, QKVLD,  bqkv, nullptr);
    // 3: fused attention (V transposed in-kernel)
    flash_kernel<<<dim3(SS_/128, BB_*NH_), blk, FL_SMEM>>>(qkv, am, ctx);
    // 4: x2 = x + ctx @ Wo^T + bo
    tc_gemm<3><<<dim3(HID_/128, TOK_/128), blk, SM3>>>(TOK_, HID_, HID_,
        ctx, HID_,  rWo, HID_,  x2, nullptr, HID_,  bo, x);
    // 5: h2 = LN2(x2)
    ln_kernel<<<TOK_, blk>>>(x2, g2, be2, h2);
    // 6: ff = gelu(h2 @ W1^T + b1)
    tc_gemm<2><<<dim3(FF_/128, TOK_/128), blk, SM3>>>(TOK_, FF_, HID_,
        h2, HID_,  rW1, HID_,  nullptr, ff, FF_,  b1, nullptr);
    // 7: out = x2 + ff @ W2^T + b2
    tc_gemm<3><<<dim3(HID_/128, TOK_/128), blk, SM3>>>(TOK_, HID_, FF_,
        ff, FF_,  rW2, FF_,  out, nullptr, HID_,  b2, x2);
}

// round 13
// speedup vs baseline: 1.2853x; 1.0967x over previous
#include <cuda_runtime.h>
#include <cuda_bf16.h>
#include <math.h>
#include <stdint.h>

#define BB_   2
#define SS_   2048
#define HID_  1024
#define NH_   16
#define HD_   64
#define FF_   4096
#define TOK_  (BB_*SS_)   // 4096
#define QKVLD 3072

// ---------------- scratch ----------------
__device__ __nv_bfloat16 g_h  [TOK_*HID_];
__device__ __nv_bfloat16 g_qkv[TOK_*3*HID_];       // [TOK, 3072] = q|k|v
__device__ __nv_bfloat16 g_ctx[TOK_*HID_];
__device__ float         g_x2 [TOK_*HID_];
__device__ __nv_bfloat16 g_h2 [TOK_*HID_];
__device__ __nv_bfloat16 g_ff [TOK_*FF_];
__device__ __nv_bfloat16 g_wb [12*1024*1024];      // bf16 weights (q|k|v|o|W1|W2)
__device__ float         g_bqkv[3*HID_];

// ---------------- helpers ----------------
__device__ __forceinline__ uint32_t bf2(float x, float y) {
    __nv_bfloat162 t = __floats2bfloat162_rn(x, y);
    return *reinterpret_cast<uint32_t*>(&t);
}
__device__ __forceinline__ uint32_t smem_u32(const void* p) {
    uint32_t a;
    asm("{ .reg .u64 t; cvta.to.shared.u64 t, %1; cvt.u32.u64 %0, t; }" : "=r"(a) : "l"(p));
    return a;
}
#define CP16(dst, src) \
    asm volatile("cp.async.cg.shared.global [%0], [%1], 16;" :: "r"(dst), "l"(src) : "memory")
#define CP_COMMIT() asm volatile("cp.async.commit_group;" ::: "memory")
#define CP_WAIT1()  asm volatile("cp.async.wait_group 1;" ::: "memory")
#define CP_WAIT0()  asm volatile("cp.async.wait_group 0;" ::: "memory")

#define LDSM4(R0, R1, R2, R3, ADDR) \
    asm volatile("ldmatrix.sync.aligned.m8n8.x4.shared.b16 {%0,%1,%2,%3}, [%4];" \
        : "=r"(R0), "=r"(R1), "=r"(R2), "=r"(R3) : "r"(ADDR))
#define LDSM4T(R0, R1, R2, R3, ADDR) \
    asm volatile("ldmatrix.sync.aligned.m8n8.x4.trans.shared.b16 {%0,%1,%2,%3}, [%4];" \
        : "=r"(R0), "=r"(R1), "=r"(R2), "=r"(R3) : "r"(ADDR))

__device__ __forceinline__ void mma16816(float* c, const uint32_t* a, uint32_t b0, uint32_t b1) {
    asm volatile(
        "mma.sync.aligned.m16n8k16.row.col.f32.bf16.bf16.f32 "
        "{%0,%1,%2,%3}, {%4,%5,%6,%7}, {%8,%9}, {%0,%1,%2,%3};"
        : "+f"(c[0]), "+f"(c[1]), "+f"(c[2]), "+f"(c[3])
        : "r"(a[0]), "r"(a[1]), "r"(a[2]), "r"(a[3]), "r"(b0), "r"(b1));
}

// ---------------- fused conversion: weights -> bf16 + bias pack ----------------
__global__ void convert_all_kernel(
    const float* __restrict__ Wq, const float* __restrict__ Wk,
    const float* __restrict__ Wv, const float* __restrict__ Wo,
    const float* __restrict__ W1, const float* __restrict__ W2,
    const float* __restrict__ bq, const float* __restrict__ bk,
    const float* __restrict__ bv,
    __nv_bfloat16* __restrict__ wb, float* __restrict__ bqkv)
{
    int bid = blockIdx.x;
    if (bid < 4096) {
        int i = bid * 256 + threadIdx.x;
        int seg = i >> 18, off = i & 262143;
        const float4* sp;
        __nv_bfloat16* dp;
        if      (seg == 0) { sp = (const float4*)Wq; dp = wb; }
        else if (seg == 1) { sp = (const float4*)Wk; dp = wb + 1024*1024; }
        else if (seg == 2) { sp = (const float4*)Wv; dp = wb + 2*1024*1024; }
        else               { sp = (const float4*)Wo; dp = wb + 3*1024*1024; }
        float4 v = sp[off];
        reinterpret_cast<uint2*>(dp)[off] = make_uint2(bf2(v.x, v.y), bf2(v.z, v.w));
    } else if (bid < 12288) {
        int i = (bid - 4096) * 256 + threadIdx.x;
        int seg = i >> 20, off = i & 1048575;
        const float4* sp = seg ? (const float4*)W2 : (const float4*)W1;
        __nv_bfloat16* dp = seg ? (wb + 8*1024*1024) : (wb + 4*1024*1024);
        float4 v = sp[off];
        reinterpret_cast<uint2*>(dp)[off] = make_uint2(bf2(v.x, v.y), bf2(v.z, v.w));
    } else {
        int i = (bid - 12288) * 256 + threadIdx.x;
        if (i < HID_)            bqkv[i] = bq[i];
        else if (i < 2 * HID_)   bqkv[i] = bk[i - HID_];
        else if (i < 3 * HID_)   bqkv[i] = bv[i - 2 * HID_];
    }
}

// ---------------- block reduction ----------------
template<bool MAX>
__device__ __forceinline__ float block_reduce_256(float v) {
    __shared__ float sh[8];
    int lane = threadIdx.x & 31, w = threadIdx.x >> 5;
    #pragma unroll
    for (int o = 16; o; o >>= 1) {
        float u = __shfl_xor_sync(0xffffffffu, v, o);
        v = MAX ? fmaxf(v, u) : v + u;
    }
    if (lane == 0) sh[w] = v;
    __syncthreads();
    if (w == 0) {
        v = sh[lane & 7];
        #pragma unroll
        for (int o = 4; o; o >>= 1) {
            float u = __shfl_xor_sync(0xffffffffu, v, o);
            v = MAX ? fmaxf(v, u) : v + u;
        }
        if (lane == 0) sh[0] = v;
    }
    __syncthreads();
    float r = sh[0];
    __syncthreads();
    return r;
}

// ---------------- LayerNorm (fp32 in -> bf16 out) ----------------
__global__ void ln_kernel(const float* __restrict__ x, const float* __restrict__ g,
                          const float* __restrict__ beta, __nv_bfloat16* __restrict__ out) {
    size_t base = (size_t)blockIdx.x * HID_;
    const float4* xp = reinterpret_cast<const float4*>(x + base);
    int t = threadIdx.x;
    float4 v = xp[t];
    float s = v.x + v.y + v.z + v.w;
    s = block_reduce_256<false>(s);
    float mean = s * (1.0f / HID_);
    float dx = v.x - mean, dy = v.y - mean, dz = v.z - mean, dw = v.w - mean;
    float q = dx*dx + dy*dy + dz*dz + dw*dw;
    q = block_reduce_256<false>(q);
    float r = rsqrtf(q * (1.0f / HID_) + 1e-5f);
    float4 gv = reinterpret_cast<const float4*>(g)[t];
    float4 bv = reinterpret_cast<const float4*>(beta)[t];
    uint2 o;
    o.x = bf2(dx * r * gv.x + bv.x, dy * r * gv.y + bv.y);
    o.y = bf2(dz * r * gv.z + bv.z, dw * r * gv.w + bv.w);
    reinterpret_cast<uint2*>(out + base)[t] = o;
}

// ---------------- flash attention: register-resident P, warps partition M ----------------
// 8 warps x 16 rows. Warp tile 16x64 in both phases; S C-frags convert in-register
// to P A-frags (C layout == A layout for m16n8k16). No P smem, no Psum, 2 barriers/iter.
#define FFS 72
#define FQ  0
#define FK  (128*FFS)
#define FV  (FK + 2*64*FFS)
#define FL_FLT ((FV + 2*64*FFS) * 2)
#define FL_SMEM (FL_FLT + 2048 * 4)

__global__ __launch_bounds__(256, 2) void flash_kernel(
    const __nv_bfloat16* __restrict__ qkv,
    const float* __restrict__ am, __nv_bfloat16* __restrict__ ctx)
{
    extern __shared__ __align__(16) char smc[];
    float* Madd = reinterpret_cast<float*>(smc + FL_FLT);

    const int tid = threadIdx.x, lane = tid & 31, wid = tid >> 5;   // wid 0..7
    const int gr = lane >> 2, c2 = (lane & 3) << 1;
    const int qq = lane >> 3, l8 = lane & 7;
    const int arow = ((qq & 1) << 3) + l8, acol = (qq >> 1) << 3;   // A ldmatrix pattern
    const int brow = ((qq >> 1) << 3) + l8, bcol = (qq & 1) << 3;   // B ldmatrix pattern
    const int tkrow = ((qq & 1) << 3) + l8, tncol = (qq >> 1) << 3; // trans-B pattern
    const int qt = blockIdx.x, bh = blockIdx.y;
    const int bb = bh >> 4, hh = bh & 15;
    const int q0 = qt * 128;
    const int mrow0 = wid * 16;

    const __nv_bfloat16* Qg = qkv + ((size_t)bb * SS_ + q0) * QKVLD + hh * 64;
    const __nv_bfloat16* Kg = qkv + (size_t)bb * SS_ * QKVLD + HID_ + hh * 64;
    const __nv_bfloat16* Vg = qkv + (size_t)bb * SS_ * QKVLD + 2 * HID_ + hh * 64;

    const uint32_t sb = smem_u32(smc);
    const uint32_t sQ = sb + FQ * 2;

    // stage Q (128x64)
    #pragma unroll
    for (int u = 0; u < 4; u++) {
        int idx = tid + u * 256;
        int r = idx >> 3, c8 = (idx & 7) << 3;
        CP16(sQ + (uint32_t)((r * FFS + c8) * 2), Qg + (size_t)r * QKVLD + c8);
    }
    CP_COMMIT();
    #pragma unroll
    for (int u = 0; u < 8; u++) {
        int i = tid + u * 256;
        Madd[i] = (__ldg(&am[(size_t)bb * SS_ + i]) - 1.0f) * 10000.0f;
    }

    auto load_kv = [&](int j, int s) {
        const int j0 = j * 64;
        uint32_t kb = sb + (uint32_t)((FK + s * 64 * FFS) * 2);
        uint32_t vb = sb + (uint32_t)((FV + s * 64 * FFS) * 2);
        #pragma unroll
        for (int u = 0; u < 2; u++) {
            int idx = tid + u * 256;
            int r = idx >> 3, c8 = (idx & 7) << 3;
            CP16(kb + (uint32_t)((r * FFS + c8) * 2), Kg + (size_t)(j0 + r) * QKVLD + c8);
        }
        #pragma unroll
        for (int u = 0; u < 2; u++) {
            int idx = tid + u * 256;
            int r = idx >> 3, c8 = (idx & 7) << 3;   // token row, dh col
            CP16(vb + (uint32_t)((r * FFS + c8) * 2), Vg + (size_t)(j0 + r) * QKVLD + c8);
        }
        CP_COMMIT();
    };
    load_kv(0, 0);

    // hoist Q fragments (constant across all KV iterations)
    asm volatile("cp.async.wait_group 1;" ::: "memory");   // Q group done
    __syncthreads();
    uint32_t qf[4][4];
    #pragma unroll
    for (int kk = 0; kk < 4; kk++) {
        int rr = mrow0 + arow;
        LDSM4(qf[kk][0], qf[kk][1], qf[kk][2], qf[kk][3],
              sQ + (uint32_t)((rr * FFS + kk * 16 + acol) * 2));
    }

    float ctxa[8][4] = {};
    float lrow0 = 0.f, lrow1 = 0.f;

    const int IT = SS_ / 64;
    for (int j = 0; j < IT; j++) {
        const int s = j & 1;
        __syncthreads();
        if (j + 1 < IT) { load_kv(j + 1, s ^ 1); CP_WAIT1(); }
        else            { CP_WAIT0(); }
        __syncthreads();

        // ---- S = Q @ K^T : 16 rows x 64 keys ----
        float sacc[8][4] = {};
        const uint32_t sKs = sb + (uint32_t)((FK + s * 64 * FFS) * 2);
        #pragma unroll
        for (int kk = 0; kk < 4; kk++) {
            uint32_t kb4[8][2];
            #pragma unroll
            for (int t4 = 0; t4 < 4; t4++) {
                int nn = t4 * 16 + brow;
                LDSM4(kb4[2*t4][0], kb4[2*t4][1], kb4[2*t4+1][0], kb4[2*t4+1][1],
                      sKs + (uint32_t)((nn * FFS + kk * 16 + bcol) * 2));
            }
            #pragma unroll
            for (int t = 0; t < 8; t++)
                mma16816(sacc[t], qf[kk], kb4[t][0], kb4[t][1]);
        }

        // ---- P = exp(s*0.125 + madd) -> in-register A-frags; row sums via shfl ----
        const int j0 = j * 64;
        float ls0 = 0.f, ls1 = 0.f;
        uint32_t pa[4][4];
        #pragma unroll
        for (int t = 0; t < 8; t++) {
            float2 md = *reinterpret_cast<const float2*>(&Madd[j0 + t * 8 + c2]);
            float p0 = __expf(fmaf(sacc[t][0], 0.125f, md.x));
            float p1 = __expf(fmaf(sacc[t][1], 0.125f, md.y));
            float p2 = __expf(fmaf(sacc[t][2], 0.125f, md.x));
            float p3 = __expf(fmaf(sacc[t][3], 0.125f, md.y));
            ls0 += p0 + p1;
            ls1 += p2 + p3;
            int kk = t >> 1;
            if ((t & 1) == 0) { pa[kk][0] = bf2(p0, p1); pa[kk][1] = bf2(p2, p3); }
            else              { pa[kk][2] = bf2(p0, p1); pa[kk][3] = bf2(p2, p3); }
        }
        ls0 += __shfl_xor_sync(0xffffffffu, ls0, 1);
        ls0 += __shfl_xor_sync(0xffffffffu, ls0, 2);
        ls1 += __shfl_xor_sync(0xffffffffu, ls1, 1);
        ls1 += __shfl_xor_sync(0xffffffffu, ls1, 2);
        lrow0 += ls0;
        lrow1 += ls1;

        // ---- ctx += P @ V : 16 rows x 64 dh ----
        const uint32_t sVs = sb + (uint32_t)((FV + s * 64 * FFS) * 2);
        #pragma unroll
        for (int kk = 0; kk < 4; kk++) {
            uint32_t vb4[8][2];
            #pragma unroll
            for (int t4 = 0; t4 < 4; t4++) {
                int kr = kk * 16 + tkrow;
                int nc = t4 * 16 + tncol;
                LDSM4T(vb4[2*t4][0], vb4[2*t4][1], vb4[2*t4+1][0], vb4[2*t4+1][1],
                       sVs + (uint32_t)((kr * FFS + nc) * 2));
            }
            #pragma unroll
            for (int t = 0; t < 8; t++)
                mma16816(ctxa[t], pa[kk], vb4[t][0], vb4[t][1]);
        }
    }

    // ---- finalize ----
    float inv0 = 1.0f / lrow0, inv1 = 1.0f / lrow1;
    size_t r0g = ((size_t)bb * SS_ + q0 + mrow0 + gr) * HID_ + hh * 64;
    size_t r1g = r0g + 8 * HID_;
    #pragma unroll
    for (int t = 0; t < 8; t++) {
        int col = t * 8 + c2;
        *reinterpret_cast<uint32_t*>(ctx + r0g + col) = bf2(ctxa[t][0] * inv0, ctxa[t][1] * inv0);
        *reinterpret_cast<uint32_t*>(ctx + r1g + col) = bf2(ctxa[t][2] * inv1, ctxa[t][3] * inv1);
    }
}

// ---------------- bf16 mma GEMM (R10 proven config) ----------------
// EPI: 0 = +bias -> bf16; 2 = gelu(+bias) -> bf16; 3 = +bias+residual -> fp32
template<int EPI>
__global__ __launch_bounds__(256, 2) void tc_gemm(
    int M, int N, int K,
    const __nv_bfloat16* __restrict__ A,  int lda,
    const __nv_bfloat16* __restrict__ Bm, int ldb,
    float* __restrict__ Cf, __nv_bfloat16* __restrict__ Cb, int ldc,
    const float* __restrict__ bias, const float* __restrict__ residual)
{
    constexpr int RS  = 72;
    constexpr int ASZ = 128 * RS;
    constexpr int STG = 2 * ASZ;
    constexpr int NT  = 4;

    extern __shared__ __align__(16) char smc[];

    const int tid  = threadIdx.x;
    const int wid  = tid >> 5, lane = tid & 31;
    const int wm   = wid >> 2, wn = wid & 3;
    const int qq   = lane >> 3, l8 = lane & 7;
    const int arow = ((qq & 1) << 3) + l8, acol = (qq >> 1) << 3;
    const int brow = ((qq >> 1) << 3) + l8, bcol = (qq & 1) << 3;
    const int row0 = blockIdx.y * 128;
    const int col0 = blockIdx.x * 128;

    const uint32_t sbase = smem_u32(smc);

    float acc[4][NT][4];
    #pragma unroll
    for (int i = 0; i < 4; i++)
        #pragma unroll
        for (int j = 0; j < NT; j++)
            #pragma unroll
            for (int e = 0; e < 4; e++) acc[i][j][e] = 0.0f;

    const int nk = K >> 6;

    auto load_stage = [&](int i, int s) {
        const int k0 = i << 6;
        uint32_t abase = sbase + (uint32_t)(s * STG) * 2u;
        uint32_t bbase = abase + (uint32_t)ASZ * 2u;
        #pragma unroll
        for (int u = 0; u < 4; u++) {
            int idx = tid + u * 256;
            int r = idx >> 3, c8 = (idx & 7) << 3;
            CP16(abase + (uint32_t)(r * RS + c8) * 2u,
                 A + (size_t)(row0 + r) * lda + k0 + c8);
        }
        #pragma unroll
        for (int u = 0; u < 4; u++) {
            int idx = tid + u * 256;
            int r = idx >> 3, c8 = (idx & 7) << 3;
            CP16(bbase + (uint32_t)(r * RS + c8) * 2u,
                 Bm + (size_t)(col0 + r) * ldb + k0 + c8);
        }
        CP_COMMIT();
    };

    load_stage(0, 0);
    load_stage(1, 1);

    int s = 0;
    for (int i = 0; i < nk; i++) {
        if (i == nk - 1) { CP_WAIT0(); } else { CP_WAIT1(); }
        __syncthreads();
        int ns = s + 2; if (ns >= 3) ns -= 3;
        if (i + 2 < nk) load_stage(i + 2, ns);

        const uint32_t sAs = sbase + (uint32_t)(s * STG) * 2u;
        const uint32_t sBs = sAs + (uint32_t)ASZ * 2u;

        #pragma unroll
        for (int kk = 0; kk < 4; kk++) {
            uint32_t af[4][4];
            #pragma unroll
            for (int mt = 0; mt < 4; mt++) {
                int rr = wm * 64 + mt * 16 + arow;
                LDSM4(af[mt][0], af[mt][1], af[mt][2], af[mt][3],
                      sAs + (uint32_t)((rr * RS + kk * 16 + acol) * 2));
            }
            uint32_t bf[NT][2];
            #pragma unroll
            for (int ntp = 0; ntp < NT / 2; ntp++) {
                int nn = wn * 32 + ntp * 16 + brow;
                LDSM4(bf[2*ntp][0], bf[2*ntp][1], bf[2*ntp+1][0], bf[2*ntp+1][1],
                      sBs + (uint32_t)((nn * RS + kk * 16 + bcol) * 2));
            }
            #pragma unroll
            for (int nt = 0; nt < NT; nt++)
                #pragma unroll
                for (int mt = 0; mt < 4; mt++)
                    mma16816(acc[mt][nt], af[mt], bf[nt][0], bf[nt][1]);
        }
        s++; if (s == 3) s = 0;
    }

    #pragma unroll
    for (int mt = 0; mt < 4; mt++) {
        #pragma unroll
        for (int nt = 0; nt < NT; nt++) {
            int r0 = row0 + wm * 64 + mt * 16 + (lane >> 2);
            int c0 = col0 + wn * 32 + nt * 8 + 2 * (lane & 3);
            #pragma unroll
            for (int half = 0; half < 2; half++) {
                int r = r0 + half * 8;
                float v0 = acc[mt][nt][2 * half + 0];
                float v1 = acc[mt][nt][2 * half + 1];
                v0 += __ldg(&bias[c0]);
                v1 += __ldg(&bias[c0 + 1]);
                if (EPI == 2) {
                    v0 = 0.5f * v0 * (1.0f + erff(v0 * 0.70710678118654752f));
                    v1 = 0.5f * v1 * (1.0f + erff(v1 * 0.70710678118654752f));
                }
                if (EPI == 3) {
                    float2 rr = *reinterpret_cast<const float2*>(
                        residual + (size_t)r * ldc + c0);
                    v0 += rr.x; v1 += rr.y;
                    float2 o; o.x = v0; o.y = v1;
                    *reinterpret_cast<float2*>(Cf + (size_t)r * ldc + c0) = o;
                } else {
                    *reinterpret_cast<uint32_t*>(Cb + (size_t)r * ldc + c0) = bf2(v0, v1);
                }
            }
        }
    }
}

// ---------------- launch ----------------
extern "C" void kernel_launch(void* const* d_in, const int* in_sizes, int n_in,
                              void* d_out, int out_size) {
    const float* x   = (const float*)d_in[0];
    const float* am  = (const float*)d_in[1];
    const float* Wq  = (const float*)d_in[2];
    const float* bq  = (const float*)d_in[3];
    const float* Wk  = (const float*)d_in[4];
    const float* bk  = (const float*)d_in[5];
    const float* Wv  = (const float*)d_in[6];
    const float* bv  = (const float*)d_in[7];
    const float* Wo  = (const float*)d_in[8];
    const float* bo  = (const float*)d_in[9];
    const float* W1  = (const float*)d_in[10];
    const float* b1  = (const float*)d_in[11];
    const float* W2  = (const float*)d_in[12];
    const float* b2  = (const float*)d_in[13];
    const float* g1  = (const float*)d_in[14];
    const float* be1 = (const float*)d_in[15];
    const float* g2  = (const float*)d_in[16];
    const float* be2 = (const float*)d_in[17];
    float* out = (float*)d_out;

    __nv_bfloat16 *h, *qkv, *ctx, *h2, *ff, *wb;
    float *x2, *bqkv;
    cudaGetSymbolAddress((void**)&h,    g_h);
    cudaGetSymbolAddress((void**)&qkv,  g_qkv);
    cudaGetSymbolAddress((void**)&ctx,  g_ctx);
    cudaGetSymbolAddress((void**)&x2,   g_x2);
    cudaGetSymbolAddress((void**)&h2,   g_h2);
    cudaGetSymbolAddress((void**)&ff,   g_ff);
    cudaGetSymbolAddress((void**)&wb,   g_wb);
    cudaGetSymbolAddress((void**)&bqkv, g_bqkv);

    __nv_bfloat16* rWqkv = wb;
    __nv_bfloat16* rWo = wb + 3 * 1024 * 1024;
    __nv_bfloat16* rW1 = wb + 4 * 1024 * 1024;
    __nv_bfloat16* rW2 = wb + 8 * 1024 * 1024;

    const int SM3 = 3 * 2 * 128 * 72 * 2;            // 110592 bytes
    cudaFuncSetAttribute(tc_gemm<0>, cudaFuncAttributeMaxDynamicSharedMemorySize, SM3);
    cudaFuncSetAttribute(tc_gemm<2>, cudaFuncAttributeMaxDynamicSharedMemorySize, SM3);
    cudaFuncSetAttribute(tc_gemm<3>, cudaFuncAttributeMaxDynamicSharedMemorySize, SM3);
    cudaFuncSetAttribute(flash_kernel, cudaFuncAttributeMaxDynamicSharedMemorySize, FL_SMEM);

    dim3 blk(256);

    convert_all_kernel<<<12300, blk>>>(Wq, Wk, Wv, Wo, W1, W2, bq, bk, bv, wb, bqkv);
    ln_kernel<<<TOK_, blk>>>(x, g1, be1, h);
    tc_gemm<0><<<dim3(QKVLD/128, TOK_/128), blk, SM3>>>(TOK_, QKVLD, HID_,
        h, HID_,  rWqkv, HID_,  nullptr, qkv, QKVLD,  bqkv, nullptr);
    flash_kernel<<<dim3(SS_/128, BB_*NH_), blk, FL_SMEM>>>(qkv, am, ctx);
    tc_gemm<3><<<dim3(HID_/128, TOK_/128), blk, SM3>>>(TOK_, HID_, HID_,
        ctx, HID_,  rWo, HID_,  x2, nullptr, HID_,  bo, x);
    ln_kernel<<<TOK_, blk>>>(x2, g2, be2, h2);
    tc_gemm<2><<<dim3(FF_/128, TOK_/128), blk, SM3>>>(TOK_, FF_, HID_,
        h2, HID_,  rW1, HID_,  nullptr, ff, FF_,  b1, nullptr);
    tc_gemm<3><<<dim3(HID_/128, TOK_/128), blk, SM3>>>(TOK_, HID_, FF_,
        ff, FF_,  rW2, FF_,  out, nullptr, HID_,  b2, x2);
}

// round 14
// speedup vs baseline: 1.2885x; 1.0025x over previous
#include <cuda_runtime.h>
#include <cuda_bf16.h>
#include <math.h>
#include <stdint.h>

#define BB_   2
#define SS_   2048
#define HID_  1024
#define NH_   16
#define HD_   64
#define FF_   4096
#define TOK_  (BB_*SS_)   // 4096
#define QKVLD 3072

// ---------------- scratch ----------------
__device__ __nv_bfloat16 g_h  [TOK_*HID_];
__device__ __nv_bfloat16 g_qkv[TOK_*3*HID_];       // [TOK, 3072] = q|k|v
__device__ __nv_bfloat16 g_ctx[TOK_*HID_];
__device__ float         g_x2 [TOK_*HID_];
__device__ __nv_bfloat16 g_h2 [TOK_*HID_];
__device__ __nv_bfloat16 g_ff [TOK_*FF_];
__device__ __nv_bfloat16 g_wb [12*1024*1024];      // bf16 weights (q|k|v|o|W1|W2)
__device__ float         g_bqkv[3*HID_];

// ---------------- helpers ----------------
__device__ __forceinline__ uint32_t bf2(float x, float y) {
    __nv_bfloat162 t = __floats2bfloat162_rn(x, y);
    return *reinterpret_cast<uint32_t*>(&t);
}
__device__ __forceinline__ uint32_t smem_u32(const void* p) {
    uint32_t a;
    asm("{ .reg .u64 t; cvta.to.shared.u64 t, %1; cvt.u32.u64 %0, t; }" : "=r"(a) : "l"(p));
    return a;
}
#define CP16(dst, src) \
    asm volatile("cp.async.cg.shared.global [%0], [%1], 16;" :: "r"(dst), "l"(src) : "memory")
#define CP_COMMIT() asm volatile("cp.async.commit_group;" ::: "memory")
#define CP_WAIT2()  asm volatile("cp.async.wait_group 2;" ::: "memory")
#define CP_WAIT1()  asm volatile("cp.async.wait_group 1;" ::: "memory")
#define CP_WAIT0()  asm volatile("cp.async.wait_group 0;" ::: "memory")

#define LDSM4(R0, R1, R2, R3, ADDR) \
    asm volatile("ldmatrix.sync.aligned.m8n8.x4.shared.b16 {%0,%1,%2,%3}, [%4];" \
        : "=r"(R0), "=r"(R1), "=r"(R2), "=r"(R3) : "r"(ADDR))
#define LDSM4T(R0, R1, R2, R3, ADDR) \
    asm volatile("ldmatrix.sync.aligned.m8n8.x4.trans.shared.b16 {%0,%1,%2,%3}, [%4];" \
        : "=r"(R0), "=r"(R1), "=r"(R2), "=r"(R3) : "r"(ADDR))

__device__ __forceinline__ void mma16816(float* c, const uint32_t* a, uint32_t b0, uint32_t b1) {
    asm volatile(
        "mma.sync.aligned.m16n8k16.row.col.f32.bf16.bf16.f32 "
        "{%0,%1,%2,%3}, {%4,%5,%6,%7}, {%8,%9}, {%0,%1,%2,%3};"
        : "+f"(c[0]), "+f"(c[1]), "+f"(c[2]), "+f"(c[3])
        : "r"(a[0]), "r"(a[1]), "r"(a[2]), "r"(a[3]), "r"(b0), "r"(b1));
}

// ---------------- fused conversion: weights -> bf16 + bias pack ----------------
__global__ void convert_all_kernel(
    const float* __restrict__ Wq, const float* __restrict__ Wk,
    const float* __restrict__ Wv, const float* __restrict__ Wo,
    const float* __restrict__ W1, const float* __restrict__ W2,
    const float* __restrict__ bq, const float* __restrict__ bk,
    const float* __restrict__ bv,
    __nv_bfloat16* __restrict__ wb, float* __restrict__ bqkv)
{
    int bid = blockIdx.x;
    if (bid < 4096) {
        int i = bid * 256 + threadIdx.x;
        int seg = i >> 18, off = i & 262143;
        const float4* sp;
        __nv_bfloat16* dp;
        if      (seg == 0) { sp = (const float4*)Wq; dp = wb; }
        else if (seg == 1) { sp = (const float4*)Wk; dp = wb + 1024*1024; }
        else if (seg == 2) { sp = (const float4*)Wv; dp = wb + 2*1024*1024; }
        else               { sp = (const float4*)Wo; dp = wb + 3*1024*1024; }
        float4 v = sp[off];
        reinterpret_cast<uint2*>(dp)[off] = make_uint2(bf2(v.x, v.y), bf2(v.z, v.w));
    } else if (bid < 12288) {
        int i = (bid - 4096) * 256 + threadIdx.x;
        int seg = i >> 20, off = i & 1048575;
        const float4* sp = seg ? (const float4*)W2 : (const float4*)W1;
        __nv_bfloat16* dp = seg ? (wb + 8*1024*1024) : (wb + 4*1024*1024);
        float4 v = sp[off];
        reinterpret_cast<uint2*>(dp)[off] = make_uint2(bf2(v.x, v.y), bf2(v.z, v.w));
    } else {
        int i = (bid - 12288) * 256 + threadIdx.x;
        if (i < HID_)            bqkv[i] = bq[i];
        else if (i < 2 * HID_)   bqkv[i] = bk[i - HID_];
        else if (i < 3 * HID_)   bqkv[i] = bv[i - 2 * HID_];
    }
}

// ---------------- block reduction ----------------
template<bool MAX>
__device__ __forceinline__ float block_reduce_256(float v) {
    __shared__ float sh[8];
    int lane = threadIdx.x & 31, w = threadIdx.x >> 5;
    #pragma unroll
    for (int o = 16; o; o >>= 1) {
        float u = __shfl_xor_sync(0xffffffffu, v, o);
        v = MAX ? fmaxf(v, u) : v + u;
    }
    if (lane == 0) sh[w] = v;
    __syncthreads();
    if (w == 0) {
        v = sh[lane & 7];
        #pragma unroll
        for (int o = 4; o; o >>= 1) {
            float u = __shfl_xor_sync(0xffffffffu, v, o);
            v = MAX ? fmaxf(v, u) : v + u;
        }
        if (lane == 0) sh[0] = v;
    }
    __syncthreads();
    float r = sh[0];
    __syncthreads();
    return r;
}

// ---------------- LayerNorm (fp32 in -> bf16 out) ----------------
__global__ void ln_kernel(const float* __restrict__ x, const float* __restrict__ g,
                          const float* __restrict__ beta, __nv_bfloat16* __restrict__ out) {
    size_t base = (size_t)blockIdx.x * HID_;
    const float4* xp = reinterpret_cast<const float4*>(x + base);
    int t = threadIdx.x;
    float4 v = xp[t];
    float s = v.x + v.y + v.z + v.w;
    s = block_reduce_256<false>(s);
    float mean = s * (1.0f / HID_);
    float dx = v.x - mean, dy = v.y - mean, dz = v.z - mean, dw = v.w - mean;
    float q = dx*dx + dy*dy + dz*dz + dw*dw;
    q = block_reduce_256<false>(q);
    float r = rsqrtf(q * (1.0f / HID_) + 1e-5f);
    float4 gv = reinterpret_cast<const float4*>(g)[t];
    float4 bv = reinterpret_cast<const float4*>(beta)[t];
    uint2 o;
    o.x = bf2(dx * r * gv.x + bv.x, dy * r * gv.y + bv.y);
    o.y = bf2(dz * r * gv.z + bv.z, dw * r * gv.w + bv.w);
    reinterpret_cast<uint2*>(out + base)[t] = o;
}

// ---------------- flash attention: register P, 3-stage KV ring, 1 barrier/iter ----------------
#define FFS 72
#define FQ  0
#define FK  (128*FFS)
#define FV  (FK + 3*64*FFS)
#define FL_FLT ((FV + 3*64*FFS) * 2)
#define FL_SMEM (FL_FLT + 2048 * 4)

__global__ __launch_bounds__(256, 2) void flash_kernel(
    const __nv_bfloat16* __restrict__ qkv,
    const float* __restrict__ am, __nv_bfloat16* __restrict__ ctx)
{
    extern __shared__ __align__(16) char smc[];
    float* Madd = reinterpret_cast<float*>(smc + FL_FLT);

    const int tid = threadIdx.x, lane = tid & 31, wid = tid >> 5;   // wid 0..7
    const int gr = lane >> 2, c2 = (lane & 3) << 1;
    const int qq = lane >> 3, l8 = lane & 7;
    const int arow = ((qq & 1) << 3) + l8, acol = (qq >> 1) << 3;
    const int brow = ((qq >> 1) << 3) + l8, bcol = (qq & 1) << 3;
    const int tkrow = ((qq & 1) << 3) + l8, tncol = (qq >> 1) << 3;
    const int qt = blockIdx.x, bh = blockIdx.y;
    const int bb = bh >> 4, hh = bh & 15;
    const int q0 = qt * 128;
    const int mrow0 = wid * 16;

    const __nv_bfloat16* Qg = qkv + ((size_t)bb * SS_ + q0) * QKVLD + hh * 64;
    const __nv_bfloat16* Kg = qkv + (size_t)bb * SS_ * QKVLD + HID_ + hh * 64;
    const __nv_bfloat16* Vg = qkv + (size_t)bb * SS_ * QKVLD + 2 * HID_ + hh * 64;

    const uint32_t sb = smem_u32(smc);
    const uint32_t sQ = sb + FQ * 2;

    // stage Q (128x64) — own group
    #pragma unroll
    for (int u = 0; u < 4; u++) {
        int idx = tid + u * 256;
        int r = idx >> 3, c8 = (idx & 7) << 3;
        CP16(sQ + (uint32_t)((r * FFS + c8) * 2), Qg + (size_t)r * QKVLD + c8);
    }
    CP_COMMIT();
    #pragma unroll
    for (int u = 0; u < 8; u++) {
        int i = tid + u * 256;
        Madd[i] = (__ldg(&am[(size_t)bb * SS_ + i]) - 1.0f) * 10000.0f;
    }

    auto load_kv = [&](int j, int s) {
        const int j0 = j * 64;
        uint32_t kb = sb + (uint32_t)((FK + s * 64 * FFS) * 2);
        uint32_t vb = sb + (uint32_t)((FV + s * 64 * FFS) * 2);
        #pragma unroll
        for (int u = 0; u < 2; u++) {
            int idx = tid + u * 256;
            int r = idx >> 3, c8 = (idx & 7) << 3;
            CP16(kb + (uint32_t)((r * FFS + c8) * 2), Kg + (size_t)(j0 + r) * QKVLD + c8);
        }
        #pragma unroll
        for (int u = 0; u < 2; u++) {
            int idx = tid + u * 256;
            int r = idx >> 3, c8 = (idx & 7) << 3;
            CP16(vb + (uint32_t)((r * FFS + c8) * 2), Vg + (size_t)(j0 + r) * QKVLD + c8);
        }
        CP_COMMIT();
    };
    load_kv(0, 0);
    load_kv(1, 1);

    // hoist Q fragments: Q group done when <=2 groups (kv0, kv1) outstanding
    CP_WAIT2();
    __syncthreads();
    uint32_t qf[4][4];
    #pragma unroll
    for (int kk = 0; kk < 4; kk++) {
        int rr = mrow0 + arow;
        LDSM4(qf[kk][0], qf[kk][1], qf[kk][2], qf[kk][3],
              sQ + (uint32_t)((rr * FFS + kk * 16 + acol) * 2));
    }

    float ctxa[8][4] = {};
    float lrow0 = 0.f, lrow1 = 0.f;

    const int IT = SS_ / 64;   // 32
    int s = 0;
    for (int j = 0; j < IT; j++) {
        if (j == IT - 1) { CP_WAIT0(); } else { CP_WAIT1(); }
        __syncthreads();                 // stage s ready; iter j-1 compute done everywhere
        int ns = s + 2; if (ns >= 3) ns -= 3;
        if (j + 2 < IT) load_kv(j + 2, ns);

        // ---- S = Q @ K^T : 16 rows x 64 keys ----
        float sacc[8][4] = {};
        const uint32_t sKs = sb + (uint32_t)((FK + s * 64 * FFS) * 2);
        #pragma unroll
        for (int kk = 0; kk < 4; kk++) {
            uint32_t kb4[8][2];
            #pragma unroll
            for (int t4 = 0; t4 < 4; t4++) {
                int nn = t4 * 16 + brow;
                LDSM4(kb4[2*t4][0], kb4[2*t4][1], kb4[2*t4+1][0], kb4[2*t4+1][1],
                      sKs + (uint32_t)((nn * FFS + kk * 16 + bcol) * 2));
            }
            #pragma unroll
            for (int t = 0; t < 8; t++)
                mma16816(sacc[t], qf[kk], kb4[t][0], kb4[t][1]);
        }

        // ---- P = exp(s*0.125 + madd) -> in-register A-frags; row sums via shfl ----
        const int j0 = j * 64;
        float ls0 = 0.f, ls1 = 0.f;
        uint32_t pa[4][4];
        #pragma unroll
        for (int t = 0; t < 8; t++) {
            float2 md = *reinterpret_cast<const float2*>(&Madd[j0 + t * 8 + c2]);
            float p0 = __expf(fmaf(sacc[t][0], 0.125f, md.x));
            float p1 = __expf(fmaf(sacc[t][1], 0.125f, md.y));
            float p2 = __expf(fmaf(sacc[t][2], 0.125f, md.x));
            float p3 = __expf(fmaf(sacc[t][3], 0.125f, md.y));
            ls0 += p0 + p1;
            ls1 += p2 + p3;
            int kk = t >> 1;
            if ((t & 1) == 0) { pa[kk][0] = bf2(p0, p1); pa[kk][1] = bf2(p2, p3); }
            else              { pa[kk][2] = bf2(p0, p1); pa[kk][3] = bf2(p2, p3); }
        }
        ls0 += __shfl_xor_sync(0xffffffffu, ls0, 1);
        ls0 += __shfl_xor_sync(0xffffffffu, ls0, 2);
        ls1 += __shfl_xor_sync(0xffffffffu, ls1, 1);
        ls1 += __shfl_xor_sync(0xffffffffu, ls1, 2);
        lrow0 += ls0;
        lrow1 += ls1;

        // ---- ctx += P @ V : 16 rows x 64 dh ----
        const uint32_t sVs = sb + (uint32_t)((FV + s * 64 * FFS) * 2);
        #pragma unroll
        for (int kk = 0; kk < 4; kk++) {
            uint32_t vb4[8][2];
            #pragma unroll
            for (int t4 = 0; t4 < 4; t4++) {
                int kr = kk * 16 + tkrow;
                int nc = t4 * 16 + tncol;
                LDSM4T(vb4[2*t4][0], vb4[2*t4][1], vb4[2*t4+1][0], vb4[2*t4+1][1],
                       sVs + (uint32_t)((kr * FFS + nc) * 2));
            }
            #pragma unroll
            for (int t = 0; t < 8; t++)
                mma16816(ctxa[t], pa[kk], vb4[t][0], vb4[t][1]);
        }
        s++; if (s == 3) s = 0;
    }

    // ---- finalize ----
    float inv0 = 1.0f / lrow0, inv1 = 1.0f / lrow1;
    size_t r0g = ((size_t)bb * SS_ + q0 + mrow0 + gr) * HID_ + hh * 64;
    size_t r1g = r0g + 8 * HID_;
    #pragma unroll
    for (int t = 0; t < 8; t++) {
        int col = t * 8 + c2;
        *reinterpret_cast<uint32_t*>(ctx + r0g + col) = bf2(ctxa[t][0] * inv0, ctxa[t][1] * inv0);
        *reinterpret_cast<uint32_t*>(ctx + r1g + col) = bf2(ctxa[t][2] * inv1, ctxa[t][3] * inv1);
    }
}

// ---------------- bf16 mma GEMM (R10 proven config) ----------------
// EPI: 0 = +bias -> bf16; 2 = gelu(+bias) -> bf16; 3 = +bias+residual -> fp32
template<int EPI>
__global__ __launch_bounds__(256, 2) void tc_gemm(
    int M, int N, int K,
    const __nv_bfloat16* __restrict__ A,  int lda,
    const __nv_bfloat16* __restrict__ Bm, int ldb,
    float* __restrict__ Cf, __nv_bfloat16* __restrict__ Cb, int ldc,
    const float* __restrict__ bias, const float* __restrict__ residual)
{
    constexpr int RS  = 72;
    constexpr int ASZ = 128 * RS;
    constexpr int STG = 2 * ASZ;
    constexpr int NT  = 4;

    extern __shared__ __align__(16) char smc[];

    const int tid  = threadIdx.x;
    const int wid  = tid >> 5, lane = tid & 31;
    const int wm   = wid >> 2, wn = wid & 3;
    const int qq   = lane >> 3, l8 = lane & 7;
    const int arow = ((qq & 1) << 3) + l8, acol = (qq >> 1) << 3;
    const int brow = ((qq >> 1) << 3) + l8, bcol = (qq & 1) << 3;
    const int row0 = blockIdx.y * 128;
    const int col0 = blockIdx.x * 128;

    const uint32_t sbase = smem_u32(smc);

    float acc[4][NT][4];
    #pragma unroll
    for (int i = 0; i < 4; i++)
        #pragma unroll
        for (int j = 0; j < NT; j++)
            #pragma unroll
            for (int e = 0; e < 4; e++) acc[i][j][e] = 0.0f;

    const int nk = K >> 6;

    auto load_stage = [&](int i, int s) {
        const int k0 = i << 6;
        uint32_t abase = sbase + (uint32_t)(s * STG) * 2u;
        uint32_t bbase = abase + (uint32_t)ASZ * 2u;
        #pragma unroll
        for (int u = 0; u < 4; u++) {
            int idx = tid + u * 256;
            int r = idx >> 3, c8 = (idx & 7) << 3;
            CP16(abase + (uint32_t)(r * RS + c8) * 2u,
                 A + (size_t)(row0 + r) * lda + k0 + c8);
        }
        #pragma unroll
        for (int u = 0; u < 4; u++) {
            int idx = tid + u * 256;
            int r = idx >> 3, c8 = (idx & 7) << 3;
            CP16(bbase + (uint32_t)(r * RS + c8) * 2u,
                 Bm + (size_t)(col0 + r) * ldb + k0 + c8);
        }
        CP_COMMIT();
    };

    load_stage(0, 0);
    load_stage(1, 1);

    int s = 0;
    for (int i = 0; i < nk; i++) {
        if (i == nk - 1) { CP_WAIT0(); } else { CP_WAIT1(); }
        __syncthreads();
        int ns = s + 2; if (ns >= 3) ns -= 3;
        if (i + 2 < nk) load_stage(i + 2, ns);

        const uint32_t sAs = sbase + (uint32_t)(s * STG) * 2u;
        const uint32_t sBs = sAs + (uint32_t)ASZ * 2u;

        #pragma unroll
        for (int kk = 0; kk < 4; kk++) {
            uint32_t af[4][4];
            #pragma unroll
            for (int mt = 0; mt < 4; mt++) {
                int rr = wm * 64 + mt * 16 + arow;
                LDSM4(af[mt][0], af[mt][1], af[mt][2], af[mt][3],
                      sAs + (uint32_t)((rr * RS + kk * 16 + acol) * 2));
            }
            uint32_t bf[NT][2];
            #pragma unroll
            for (int ntp = 0; ntp < NT / 2; ntp++) {
                int nn = wn * 32 + ntp * 16 + brow;
                LDSM4(bf[2*ntp][0], bf[2*ntp][1], bf[2*ntp+1][0], bf[2*ntp+1][1],
                      sBs + (uint32_t)((nn * RS + kk * 16 + bcol) * 2));
            }
            #pragma unroll
            for (int nt = 0; nt < NT; nt++)
                #pragma unroll
                for (int mt = 0; mt < 4; mt++)
                    mma16816(acc[mt][nt], af[mt], bf[nt][0], bf[nt][1]);
        }
        s++; if (s == 3) s = 0;
    }

    #pragma unroll
    for (int mt = 0; mt < 4; mt++) {
        #pragma unroll
        for (int nt = 0; nt < NT; nt++) {
            int r0 = row0 + wm * 64 + mt * 16 + (lane >> 2);
            int c0 = col0 + wn * 32 + nt * 8 + 2 * (lane & 3);
            #pragma unroll
            for (int half = 0; half < 2; half++) {
                int r = r0 + half * 8;
                float v0 = acc[mt][nt][2 * half + 0];
                float v1 = acc[mt][nt][2 * half + 1];
                v0 += __ldg(&bias[c0]);
                v1 += __ldg(&bias[c0 + 1]);
                if (EPI == 2) {
                    v0 = 0.5f * v0 * (1.0f + erff(v0 * 0.70710678118654752f));
                    v1 = 0.5f * v1 * (1.0f + erff(v1 * 0.70710678118654752f));
                }
                if (EPI == 3) {
                    float2 rr = *reinterpret_cast<const float2*>(
                        residual + (size_t)r * ldc + c0);
                    v0 += rr.x; v1 += rr.y;
                    float2 o; o.x = v0; o.y = v1;
                    *reinterpret_cast<float2*>(Cf + (size_t)r * ldc + c0) = o;
                } else {
                    *reinterpret_cast<uint32_t*>(Cb + (size_t)r * ldc + c0) = bf2(v0, v1);
                }
            }
        }
    }
}

// ---------------- launch ----------------
extern "C" void kernel_launch(void* const* d_in, const int* in_sizes, int n_in,
                              void* d_out, int out_size) {
    const float* x   = (const float*)d_in[0];
    const float* am  = (const float*)d_in[1];
    const float* Wq  = (const float*)d_in[2];
    const float* bq  = (const float*)d_in[3];
    const float* Wk  = (const float*)d_in[4];
    const float* bk  = (const float*)d_in[5];
    const float* Wv  = (const float*)d_in[6];
    const float* bv  = (const float*)d_in[7];
    const float* Wo  = (const float*)d_in[8];
    const float* bo  = (const float*)d_in[9];
    const float* W1  = (const float*)d_in[10];
    const float* b1  = (const float*)d_in[11];
    const float* W2  = (const float*)d_in[12];
    const float* b2  = (const float*)d_in[13];
    const float* g1  = (const float*)d_in[14];
    const float* be1 = (const float*)d_in[15];
    const float* g2  = (const float*)d_in[16];
    const float* be2 = (const float*)d_in[17];
    float* out = (float*)d_out;

    __nv_bfloat16 *h, *qkv, *ctx, *h2, *ff, *wb;
    float *x2, *bqkv;
    cudaGetSymbolAddress((void**)&h,    g_h);
    cudaGetSymbolAddress((void**)&qkv,  g_qkv);
    cudaGetSymbolAddress((void**)&ctx,  g_ctx);
    cudaGetSymbolAddress((void**)&x2,   g_x2);
    cudaGetSymbolAddress((void**)&h2,   g_h2);
    cudaGetSymbolAddress((void**)&ff,   g_ff);
    cudaGetSymbolAddress((void**)&wb,   g_wb);
    cudaGetSymbolAddress((void**)&bqkv, g_bqkv);

    __nv_bfloat16* rWqkv = wb;
    __nv_bfloat16* rWo = wb + 3 * 1024 * 1024;
    __nv_bfloat16* rW1 = wb + 4 * 1024 * 1024;
    __nv_bfloat16* rW2 = wb + 8 * 1024 * 1024;

    const int SM3 = 3 * 2 * 128 * 72 * 2;            // 110592 bytes
    cudaFuncSetAttribute(tc_gemm<0>, cudaFuncAttributeMaxDynamicSharedMemorySize, SM3);
    cudaFuncSetAttribute(tc_gemm<2>, cudaFuncAttributeMaxDynamicSharedMemorySize, SM3);
    cudaFuncSetAttribute(tc_gemm<3>, cudaFuncAttributeMaxDynamicSharedMemorySize, SM3);
    cudaFuncSetAttribute(flash_kernel, cudaFuncAttributeMaxDynamicSharedMemorySize, FL_SMEM);

    dim3 blk(256);

    convert_all_kernel<<<12300, blk>>>(Wq, Wk, Wv, Wo, W1, W2, bq, bk, bv, wb, bqkv);
    ln_kernel<<<TOK_, blk>>>(x, g1, be1, h);
    tc_gemm<0><<<dim3(QKVLD/128, TOK_/128), blk, SM3>>>(TOK_, QKVLD, HID_,
        h, HID_,  rWqkv, HID_,  nullptr, qkv, QKVLD,  bqkv, nullptr);
    flash_kernel<<<dim3(SS_/128, BB_*NH_), blk, FL_SMEM>>>(qkv, am, ctx);
    tc_gemm<3><<<dim3(HID_/128, TOK_/128), blk, SM3>>>(TOK_, HID_, HID_,
        ctx, HID_,  rWo, HID_,  x2, nullptr, HID_,  bo, x);
    ln_kernel<<<TOK_, blk>>>(x2, g2, be2, h2);
    tc_gemm<2><<<dim3(FF_/128, TOK_/128), blk, SM3>>>(TOK_, FF_, HID_,
        h2, HID_,  rW1, HID_,  nullptr, ff, FF_,  b1, nullptr);
    tc_gemm<3><<<dim3(HID_/128, TOK_/128), blk, SM3>>>(TOK_, HID_, FF_,
        ff, FF_,  rW2, FF_,  out, nullptr, HID_,  b2, x2);
}